// round 1
// baseline (speedup 1.0000x reference)
#include <cuda_runtime.h>
#include <cuda_bf16.h>
#include <math.h>

// Problem constants
#define BB 4
#define LL 13125
#define MM (BB * LL)      // 52500 rows
#define DD 256
#define NH 8
#define HD 32
#define NLV 3
#define NPT 4
#define DFF 1024
#define EPS 1e-5f

// Level shapes (H, W) and row starts within L
__device__ __constant__ int c_H[NLV] = {100, 50, 25};
__device__ __constant__ int c_W[NLV] = {100, 50, 25};
__device__ __constant__ int c_start[NLV] = {0, 10000, 12500};

// ---------------- scratch (device globals; no allocation) ----------------
__device__ float g_q[MM * DD];        // q = src + pos; later reused as attn_out tmp
__device__ float g_value[MM * DD];    // value = src@Wv+bv; later reused as ff2 tmp
__device__ float g_off[MM * 192];
__device__ float g_attn[MM * 96];
__device__ float g_samp[MM * DD];
__device__ float g_x[MM * DD];
__device__ float g_h[MM * DFF];

// ---------------- elementwise add ----------------
__global__ void add_kernel(const float* __restrict__ a, const float* __restrict__ b,
                           float* __restrict__ out, int n) {
    int i = blockIdx.x * blockDim.x + threadIdx.x;
    if (i < n) out[i] = a[i] + b[i];
}

// ---------------- SGEMM: C[M,N] = A[M,K] @ W[K,N] + bias (optional relu) ----------------
// BM=BN=128, BK=8, 256 threads, 8x8 per thread.
template <bool RELU>
__global__ void __launch_bounds__(256)
gemm_bias(const float* __restrict__ A, const float* __restrict__ W,
          const float* __restrict__ bias, float* __restrict__ C,
          int Mdim, int N, int K) {
    __shared__ float As[8][128];
    __shared__ float Ws[8][128];

    const int tid = threadIdx.x;
    const int bm = blockIdx.y * 128;
    const int bn = blockIdx.x * 128;
    const int tx = tid & 15;   // 0..15 -> N tile
    const int ty = tid >> 4;   // 0..15 -> M tile

    float acc[8][8];
#pragma unroll
    for (int i = 0; i < 8; i++)
#pragma unroll
        for (int j = 0; j < 8; j++) acc[i][j] = 0.f;

    const int arow = tid >> 1;          // 0..127
    const int acol = (tid & 1) * 4;     // 0 or 4
    const int wrow = tid >> 5;          // 0..7
    const int wcol = (tid & 31) * 4;    // 0..124

    for (int k0 = 0; k0 < K; k0 += 8) {
        // load A tile (128 x 8), transposed into As[k][m]
        {
            int grow = bm + arow;
            float4 v = make_float4(0.f, 0.f, 0.f, 0.f);
            if (grow < Mdim)
                v = *(const float4*)&A[(size_t)grow * K + k0 + acol];
            As[acol + 0][arow] = v.x;
            As[acol + 1][arow] = v.y;
            As[acol + 2][arow] = v.z;
            As[acol + 3][arow] = v.w;
        }
        // load W tile (8 x 128)
        {
            float4 v = make_float4(0.f, 0.f, 0.f, 0.f);
            if (bn + wcol < N)
                v = *(const float4*)&W[(size_t)(k0 + wrow) * N + bn + wcol];
            *(float4*)&Ws[wrow][wcol] = v;
        }
        __syncthreads();

#pragma unroll
        for (int k = 0; k < 8; k++) {
            float4 a0 = *(const float4*)&As[k][ty * 8];
            float4 a1 = *(const float4*)&As[k][ty * 8 + 4];
            float4 w0 = *(const float4*)&Ws[k][tx * 8];
            float4 w1 = *(const float4*)&Ws[k][tx * 8 + 4];
            float av[8] = {a0.x, a0.y, a0.z, a0.w, a1.x, a1.y, a1.z, a1.w};
            float wv[8] = {w0.x, w0.y, w0.z, w0.w, w1.x, w1.y, w1.z, w1.w};
#pragma unroll
            for (int i = 0; i < 8; i++)
#pragma unroll
                for (int j = 0; j < 8; j++)
                    acc[i][j] = fmaf(av[i], wv[j], acc[i][j]);
        }
        __syncthreads();
    }

#pragma unroll
    for (int i = 0; i < 8; i++) {
        int row = bm + ty * 8 + i;
        if (row >= Mdim) continue;
#pragma unroll
        for (int j = 0; j < 8; j++) {
            int col = bn + tx * 8 + j;
            if (col < N) {
                float v = acc[i][j] + bias[col];
                if (RELU) v = fmaxf(v, 0.f);
                C[(size_t)row * N + col] = v;
            }
        }
    }
}

// ---------------- deformable attention core ----------------
// One block per query row; 8 warps = 8 heads; lane = HD channel.
__global__ void __launch_bounds__(256)
deform_kernel(const float* __restrict__ value,   // [B,L,NH,HD]
              const float* __restrict__ refp,    // [B,L,NL,2]
              const float* __restrict__ off,     // [M,192]
              const float* __restrict__ logits,  // [M,96]
              float* __restrict__ out) {         // [M,256]
    const int row = blockIdx.x;
    const int h = threadIdx.y;
    const int lane = threadIdx.x;
    const int b = row / LL;

    // softmax over 12 points for this head (warp-level)
    const float* lg = logits + (size_t)row * 96 + h * 12;
    float lv = (lane < 12) ? lg[lane] : -INFINITY;
    float m = lv;
#pragma unroll
    for (int s = 16; s > 0; s >>= 1) m = fmaxf(m, __shfl_xor_sync(0xffffffffu, m, s));
    float e = (lane < 12) ? __expf(lv - m) : 0.f;
    float ssum = e;
#pragma unroll
    for (int s = 16; s > 0; s >>= 1) ssum += __shfl_xor_sync(0xffffffffu, ssum, s);
    float w12 = e / ssum;

    const float* offrow = off + (size_t)row * 192 + h * 24;
    const float* refrow = refp + (size_t)row * NLV * 2;

    float acc = 0.f;

#pragma unroll
    for (int l = 0; l < NLV; l++) {
        const int Hh = c_H[l], Ww = c_W[l], st = c_start[l];
        const float rx = refrow[l * 2 + 0];
        const float ry = refrow[l * 2 + 1];
#pragma unroll
        for (int p = 0; p < NPT; p++) {
            float ox = offrow[(l * NPT + p) * 2 + 0];
            float oy = offrow[(l * NPT + p) * 2 + 1];
            float aw = __shfl_sync(0xffffffffu, w12, l * NPT + p);
            // loc in [0,1] -> pixel coords (align_corners=False)
            float x = (rx + ox / (float)Ww) * (float)Ww - 0.5f;
            float y = (ry + oy / (float)Hh) * (float)Hh - 0.5f;
            float x0f = floorf(x), y0f = floorf(y);
            int x0 = (int)x0f, y0 = (int)y0f;
            int x1 = x0 + 1, y1 = y0 + 1;
            float wx1 = x - x0f, wy1 = y - y0f;
            float wx0 = 1.f - wx1, wy0 = 1.f - wy1;

            float s00 = 0.f, s10 = 0.f, s01 = 0.f, s11 = 0.f;
            bool vx0 = (x0 >= 0) & (x0 < Ww);
            bool vx1 = (x1 >= 0) & (x1 < Ww);
            bool vy0 = (y0 >= 0) & (y0 < Hh);
            bool vy1 = (y1 >= 0) & (y1 < Hh);
            if (vx0 & vy0)
                s00 = value[(((size_t)(b * LL + st + y0 * Ww + x0)) * NH + h) * HD + lane];
            if (vx1 & vy0)
                s10 = value[(((size_t)(b * LL + st + y0 * Ww + x1)) * NH + h) * HD + lane];
            if (vx0 & vy1)
                s01 = value[(((size_t)(b * LL + st + y1 * Ww + x0)) * NH + h) * HD + lane];
            if (vx1 & vy1)
                s11 = value[(((size_t)(b * LL + st + y1 * Ww + x1)) * NH + h) * HD + lane];

            float bil = s00 * (wx0 * wy0) + s10 * (wx1 * wy0) +
                        s01 * (wx0 * wy1) + s11 * (wx1 * wy1);
            acc = fmaf(aw, bil, acc);
        }
    }
    out[(size_t)row * DD + h * HD + lane] = acc;
}

// ---------------- fused add + LayerNorm ----------------
// out = LN(a + b) * g + beta ; one block of 256 per row (D=256)
__global__ void __launch_bounds__(256)
add_ln_kernel(const float* __restrict__ a, const float* __restrict__ b,
              const float* __restrict__ gamma, const float* __restrict__ beta,
              float* __restrict__ out) {
    const int row = blockIdx.x;
    const int t = threadIdx.x;
    float v = a[(size_t)row * DD + t] + b[(size_t)row * DD + t];

    // block reduce sum and sumsq
    float s = v, sq = v * v;
#pragma unroll
    for (int d = 16; d > 0; d >>= 1) {
        s += __shfl_xor_sync(0xffffffffu, s, d);
        sq += __shfl_xor_sync(0xffffffffu, sq, d);
    }
    __shared__ float ws[8], wsq[8];
    int wid = t >> 5, lane = t & 31;
    if (lane == 0) { ws[wid] = s; wsq[wid] = sq; }
    __syncthreads();
    if (t < 32) {
        float s2 = (t < 8) ? ws[t] : 0.f;
        float sq2 = (t < 8) ? wsq[t] : 0.f;
#pragma unroll
        for (int d = 4; d > 0; d >>= 1) {
            s2 += __shfl_xor_sync(0xffffffffu, s2, d);
            sq2 += __shfl_xor_sync(0xffffffffu, sq2, d);
        }
        if (t == 0) { ws[0] = s2; wsq[0] = sq2; }
    }
    __syncthreads();
    float mean = ws[0] * (1.f / DD);
    float var = wsq[0] * (1.f / DD) - mean * mean;
    float inv = rsqrtf(var + EPS);
    out[(size_t)row * DD + t] = (v - mean) * inv * gamma[t] + beta[t];
}

// ---------------- launch ----------------
extern "C" void kernel_launch(void* const* d_in, const int* in_sizes, int n_in,
                              void* d_out, int out_size) {
    const float* src  = (const float*)d_in[0];
    const float* pos  = (const float*)d_in[1];
    const float* refp = (const float*)d_in[2];
    const float* Wv   = (const float*)d_in[3];
    const float* bv   = (const float*)d_in[4];
    const float* Woff = (const float*)d_in[5];
    const float* boff = (const float*)d_in[6];
    const float* Wattn= (const float*)d_in[7];
    const float* battn= (const float*)d_in[8];
    const float* Wout = (const float*)d_in[9];
    const float* bout = (const float*)d_in[10];
    const float* g1   = (const float*)d_in[11];
    const float* b1   = (const float*)d_in[12];
    const float* Wff1 = (const float*)d_in[13];
    const float* bff1 = (const float*)d_in[14];
    const float* Wff2 = (const float*)d_in[15];
    const float* bff2 = (const float*)d_in[16];
    const float* g2   = (const float*)d_in[17];
    const float* b2   = (const float*)d_in[18];
    float* out = (float*)d_out;

    float *q, *val, *off, *attn, *samp, *x, *h;
    cudaGetSymbolAddress((void**)&q, g_q);
    cudaGetSymbolAddress((void**)&val, g_value);
    cudaGetSymbolAddress((void**)&off, g_off);
    cudaGetSymbolAddress((void**)&attn, g_attn);
    cudaGetSymbolAddress((void**)&samp, g_samp);
    cudaGetSymbolAddress((void**)&x, g_x);
    cudaGetSymbolAddress((void**)&h, g_h);

    const int n = MM * DD;

    // 1. q = src + pos
    add_kernel<<<(n + 255) / 256, 256>>>(src, pos, q, n);

    dim3 blk(256);
    auto grid_for = [](int Mdim, int N) {
        return dim3((N + 127) / 128, (Mdim + 127) / 128);
    };

    // 2. value = src @ Wv + bv
    gemm_bias<false><<<grid_for(MM, DD), blk>>>(src, Wv, bv, val, MM, DD, DD);
    // 3. off = q @ Woff + boff
    gemm_bias<false><<<grid_for(MM, 192), blk>>>(q, Woff, boff, off, MM, 192, DD);
    // 4. attn logits = q @ Wattn + battn
    gemm_bias<false><<<grid_for(MM, 96), blk>>>(q, Wattn, battn, attn, MM, 96, DD);

    // 5. deformable sampling
    deform_kernel<<<MM, dim3(32, 8)>>>(val, refp, off, attn, samp);

    // 6. attn_out = samp @ Wout + bout  (reuse q as tmp)
    gemm_bias<false><<<grid_for(MM, DD), blk>>>(samp, Wout, bout, q, MM, DD, DD);

    // 7. x = LN(src + attn_out)
    add_ln_kernel<<<MM, 256>>>(src, q, g1, b1, x);

    // 8. hdn = relu(x @ Wff1 + bff1)
    gemm_bias<true><<<grid_for(MM, DFF), blk>>>(x, Wff1, bff1, h, MM, DFF, DD);

    // 9. ff = hdn @ Wff2 + bff2  (reuse val as tmp)
    gemm_bias<false><<<grid_for(MM, DD), blk>>>(h, Wff2, bff2, val, MM, DD, DFF);

    // 10. out = LN(x + ff)
    add_ln_kernel<<<MM, 256>>>(x, val, g2, b2, out);
}

// round 3
// speedup vs baseline: 1.5327x; 1.5327x over previous
#include <cuda_runtime.h>
#include <cuda_bf16.h>
#include <cstdint>
#include <math.h>

// Problem constants
#define BB 4
#define LL 13125
#define MM (BB * LL)      // 52500 rows
#define DD 256
#define NH 8
#define HD 32
#define NLV 3
#define NPT 4
#define DFF 1024
#define EPS 1e-5f

__device__ __constant__ int c_H[NLV] = {100, 50, 25};
__device__ __constant__ int c_W[NLV] = {100, 50, 25};
__device__ __constant__ int c_start[NLV] = {0, 10000, 12500};

// ---------------- scratch ----------------
__device__ float g_q[MM * DD];
__device__ float g_value[MM * DD];
__device__ float g_off[MM * 192];
__device__ float g_attn[MM * 96];
__device__ float g_samp[MM * DD];
__device__ float g_x[MM * DD];
__device__ float g_h[MM * DFF];

// ---------------- elementwise add ----------------
__global__ void add_kernel(const float* __restrict__ a, const float* __restrict__ b,
                           float* __restrict__ out, int n) {
    int i = blockIdx.x * blockDim.x + threadIdx.x;
    if (i < n) out[i] = a[i] + b[i];
}

// ================= TF32 tensor-core GEMM =================
// C[M,N] = A[M,K] @ W[K,N] + bias, optional ReLU.
// BM=128, BN=128, BK=32, 256 threads (8 warps, 2Mx4N), warp tile 64x32,
// mma.sync.m16n8k8.tf32, 2-stage cp.async pipeline.

#define BM 128
#define BN 128
#define BK 32
#define A_STRIDE 36   // floats per smem A row  -> bank = 4g+t (conflict-free)
#define B_STRIDE 132  // floats per smem B row  -> bank = 4t+g (conflict-free)
#define ASZ (BM * A_STRIDE)
#define BSZ (BK * B_STRIDE)
#define GEMM_SMEM_BYTES (2 * (ASZ + BSZ) * 4)

__device__ __forceinline__ void cp_async16(void* smem_ptr, const void* gmem_ptr, bool valid) {
    uint32_t saddr = (uint32_t)__cvta_generic_to_shared(smem_ptr);
    int sz = valid ? 16 : 0;
    asm volatile("cp.async.cg.shared.global [%0], [%1], 16, %2;\n"
                 :: "r"(saddr), "l"(gmem_ptr), "r"(sz));
}
__device__ __forceinline__ void cp_commit() {
    asm volatile("cp.async.commit_group;\n");
}
template <int N>
__device__ __forceinline__ void cp_wait() {
    asm volatile("cp.async.wait_group %0;\n" :: "n"(N));
}
__device__ __forceinline__ uint32_t f2tf32(float v) {
    uint32_t r;
    asm("cvt.rna.tf32.f32 %0, %1;\n" : "=r"(r) : "f"(v));
    return r;
}

template <bool RELU>
__global__ void __launch_bounds__(256)
gemm_tf32(const float* __restrict__ A, const float* __restrict__ W,
          const float* __restrict__ bias, float* __restrict__ C,
          int Mdim, int N, int K) {
    extern __shared__ float sm[];
    float* As[2] = { sm, sm + ASZ };
    float* Bs[2] = { sm + 2 * ASZ, sm + 2 * ASZ + BSZ };

    const int tid = threadIdx.x;
    const int lane = tid & 31;
    const int wid = tid >> 5;
    const int warpM = wid & 1;        // 0..1
    const int warpN = wid >> 1;       // 0..3
    const int g = lane >> 2;          // 0..7
    const int t4 = lane & 3;          // 0..3

    const int bm = blockIdx.y * BM;
    const int bn = blockIdx.x * BN;

    // A load mapping: row = tid>>1, cols (tid&1)*16 + 4*i
    const int a_row = tid >> 1;
    const int a_col0 = (tid & 1) * 16;
    // B load mapping: krow = tid>>3, cols (tid&7)*16 + 4*i
    const int b_krow = tid >> 3;
    const int b_col0 = (tid & 7) * 16;

    const bool a_row_ok = (bm + a_row) < Mdim;
    const int a_grow = a_row_ok ? (bm + a_row) : 0;

    float acc[4][4][4];
#pragma unroll
    for (int i = 0; i < 4; i++)
#pragma unroll
        for (int j = 0; j < 4; j++)
#pragma unroll
            for (int r = 0; r < 4; r++) acc[i][j][r] = 0.f;

    const int KT = K / BK;

    // prologue: load tile 0
    {
        const float* ag = A + (size_t)a_grow * K + a_col0;
#pragma unroll
        for (int i = 0; i < 4; i++)
            cp_async16(&As[0][a_row * A_STRIDE + a_col0 + 4 * i], ag + 4 * i, a_row_ok);
        const float* bg = W + (size_t)b_krow * N + bn + b_col0;
#pragma unroll
        for (int i = 0; i < 4; i++)
            cp_async16(&Bs[0][b_krow * B_STRIDE + b_col0 + 4 * i], bg + 4 * i,
                       (bn + b_col0 + 4 * i) < N);
        cp_commit();
    }

    for (int kt = 0; kt < KT; kt++) {
        if (kt + 1 < KT) {
            const int k0 = (kt + 1) * BK;
            const int s = (kt + 1) & 1;
            const float* ag = A + (size_t)a_grow * K + k0 + a_col0;
#pragma unroll
            for (int i = 0; i < 4; i++)
                cp_async16(&As[s][a_row * A_STRIDE + a_col0 + 4 * i], ag + 4 * i, a_row_ok);
            const float* bg = W + (size_t)(k0 + b_krow) * N + bn + b_col0;
#pragma unroll
            for (int i = 0; i < 4; i++)
                cp_async16(&Bs[s][b_krow * B_STRIDE + b_col0 + 4 * i], bg + 4 * i,
                           (bn + b_col0 + 4 * i) < N);
            cp_commit();
            cp_wait<1>();
        } else {
            cp_wait<0>();
        }
        __syncthreads();

        const float* Asm = As[kt & 1];
        const float* Bsm = Bs[kt & 1];

#pragma unroll
        for (int ks = 0; ks < 4; ks++) {
            const int k = ks * 8;
            uint32_t af[4][4];
#pragma unroll
            for (int mt = 0; mt < 4; mt++) {
                const int row = warpM * 64 + mt * 16;
                af[mt][0] = f2tf32(Asm[(row + g) * A_STRIDE + k + t4]);
                af[mt][1] = f2tf32(Asm[(row + g + 8) * A_STRIDE + k + t4]);
                af[mt][2] = f2tf32(Asm[(row + g) * A_STRIDE + k + t4 + 4]);
                af[mt][3] = f2tf32(Asm[(row + g + 8) * A_STRIDE + k + t4 + 4]);
            }
            uint32_t bf[4][2];
#pragma unroll
            for (int nt = 0; nt < 4; nt++) {
                const int col = warpN * 32 + nt * 8 + g;
                bf[nt][0] = f2tf32(Bsm[(k + t4) * B_STRIDE + col]);
                bf[nt][1] = f2tf32(Bsm[(k + t4 + 4) * B_STRIDE + col]);
            }
#pragma unroll
            for (int mt = 0; mt < 4; mt++)
#pragma unroll
                for (int nt = 0; nt < 4; nt++) {
                    asm volatile(
                        "mma.sync.aligned.m16n8k8.row.col.f32.tf32.tf32.f32 "
                        "{%0,%1,%2,%3}, {%4,%5,%6,%7}, {%8,%9}, {%0,%1,%2,%3};\n"
                        : "+f"(acc[mt][nt][0]), "+f"(acc[mt][nt][1]),
                          "+f"(acc[mt][nt][2]), "+f"(acc[mt][nt][3])
                        : "r"(af[mt][0]), "r"(af[mt][1]), "r"(af[mt][2]), "r"(af[mt][3]),
                          "r"(bf[nt][0]), "r"(bf[nt][1]));
                }
        }
        __syncthreads();
    }

    // epilogue
#pragma unroll
    for (int mt = 0; mt < 4; mt++) {
        const int row0 = bm + warpM * 64 + mt * 16 + g;
#pragma unroll
        for (int nt = 0; nt < 4; nt++) {
            const int col0 = bn + warpN * 32 + nt * 8 + 2 * t4;
            if (col0 < N) {
                const float bx = bias[col0];
                const float by = bias[col0 + 1];
                if (row0 < Mdim) {
                    float v0 = acc[mt][nt][0] + bx;
                    float v1 = acc[mt][nt][1] + by;
                    if (RELU) { v0 = fmaxf(v0, 0.f); v1 = fmaxf(v1, 0.f); }
                    *(float2*)&C[(size_t)row0 * N + col0] = make_float2(v0, v1);
                }
                if (row0 + 8 < Mdim) {
                    float v2 = acc[mt][nt][2] + bx;
                    float v3 = acc[mt][nt][3] + by;
                    if (RELU) { v2 = fmaxf(v2, 0.f); v3 = fmaxf(v3, 0.f); }
                    *(float2*)&C[(size_t)(row0 + 8) * N + col0] = make_float2(v2, v3);
                }
            }
        }
    }
}

// ---------------- deformable attention core ----------------
__global__ void __launch_bounds__(256)
deform_kernel(const float* __restrict__ value,   // [B,L,NH,HD]
              const float* __restrict__ refp,    // [B,L,NL,2]
              const float* __restrict__ off,     // [M,192]
              const float* __restrict__ logits,  // [M,96]
              float* __restrict__ out) {         // [M,256]
    const int row = blockIdx.x;
    const int h = threadIdx.y;
    const int lane = threadIdx.x;
    const int b = row / LL;

    const float* lg = logits + (size_t)row * 96 + h * 12;
    float lv = (lane < 12) ? lg[lane] : -INFINITY;
    float m = lv;
#pragma unroll
    for (int s = 16; s > 0; s >>= 1) m = fmaxf(m, __shfl_xor_sync(0xffffffffu, m, s));
    float e = (lane < 12) ? __expf(lv - m) : 0.f;
    float ssum = e;
#pragma unroll
    for (int s = 16; s > 0; s >>= 1) ssum += __shfl_xor_sync(0xffffffffu, ssum, s);
    float w12 = e / ssum;

    const float* offrow = off + (size_t)row * 192 + h * 24;
    const float* refrow = refp + (size_t)row * NLV * 2;

    float acc = 0.f;

#pragma unroll
    for (int l = 0; l < NLV; l++) {
        const int Hh = c_H[l], Ww = c_W[l], st = c_start[l];
        const float rx = refrow[l * 2 + 0];
        const float ry = refrow[l * 2 + 1];
#pragma unroll
        for (int p = 0; p < NPT; p++) {
            float ox = offrow[(l * NPT + p) * 2 + 0];
            float oy = offrow[(l * NPT + p) * 2 + 1];
            float aw = __shfl_sync(0xffffffffu, w12, l * NPT + p);
            float x = (rx + ox / (float)Ww) * (float)Ww - 0.5f;
            float y = (ry + oy / (float)Hh) * (float)Hh - 0.5f;
            float x0f = floorf(x), y0f = floorf(y);
            int x0 = (int)x0f, y0 = (int)y0f;
            int x1 = x0 + 1, y1 = y0 + 1;
            float wx1 = x - x0f, wy1 = y - y0f;
            float wx0 = 1.f - wx1, wy0 = 1.f - wy1;

            float s00 = 0.f, s10 = 0.f, s01 = 0.f, s11 = 0.f;
            bool vx0 = (x0 >= 0) & (x0 < Ww);
            bool vx1 = (x1 >= 0) & (x1 < Ww);
            bool vy0 = (y0 >= 0) & (y0 < Hh);
            bool vy1 = (y1 >= 0) & (y1 < Hh);
            if (vx0 & vy0)
                s00 = value[(((size_t)(b * LL + st + y0 * Ww + x0)) * NH + h) * HD + lane];
            if (vx1 & vy0)
                s10 = value[(((size_t)(b * LL + st + y0 * Ww + x1)) * NH + h) * HD + lane];
            if (vx0 & vy1)
                s01 = value[(((size_t)(b * LL + st + y1 * Ww + x0)) * NH + h) * HD + lane];
            if (vx1 & vy1)
                s11 = value[(((size_t)(b * LL + st + y1 * Ww + x1)) * NH + h) * HD + lane];

            float bil = s00 * (wx0 * wy0) + s10 * (wx1 * wy0) +
                        s01 * (wx0 * wy1) + s11 * (wx1 * wy1);
            acc = fmaf(aw, bil, acc);
        }
    }
    out[(size_t)row * DD + h * HD + lane] = acc;
}

// ---------------- fused add + LayerNorm ----------------
__global__ void __launch_bounds__(256)
add_ln_kernel(const float* __restrict__ a, const float* __restrict__ b,
              const float* __restrict__ gamma, const float* __restrict__ beta,
              float* __restrict__ out) {
    const int row = blockIdx.x;
    const int t = threadIdx.x;
    float v = a[(size_t)row * DD + t] + b[(size_t)row * DD + t];

    float s = v, sq = v * v;
#pragma unroll
    for (int d = 16; d > 0; d >>= 1) {
        s += __shfl_xor_sync(0xffffffffu, s, d);
        sq += __shfl_xor_sync(0xffffffffu, sq, d);
    }
    __shared__ float ws[8], wsq[8];
    int wid = t >> 5, lane = t & 31;
    if (lane == 0) { ws[wid] = s; wsq[wid] = sq; }
    __syncthreads();
    if (t < 32) {
        float s2 = (t < 8) ? ws[t] : 0.f;
        float sq2 = (t < 8) ? wsq[t] : 0.f;
#pragma unroll
        for (int d = 4; d > 0; d >>= 1) {
            s2 += __shfl_xor_sync(0xffffffffu, s2, d);
            sq2 += __shfl_xor_sync(0xffffffffu, sq2, d);
        }
        if (t == 0) { ws[0] = s2; wsq[0] = sq2; }
    }
    __syncthreads();
    float mean = ws[0] * (1.f / DD);
    float var = wsq[0] * (1.f / DD) - mean * mean;
    float inv = rsqrtf(var + EPS);
    out[(size_t)row * DD + t] = (v - mean) * inv * gamma[t] + beta[t];
}

// ---------------- launch ----------------
extern "C" void kernel_launch(void* const* d_in, const int* in_sizes, int n_in,
                              void* d_out, int out_size) {
    const float* src  = (const float*)d_in[0];
    const float* pos  = (const float*)d_in[1];
    const float* refp = (const float*)d_in[2];
    const float* Wv   = (const float*)d_in[3];
    const float* bv   = (const float*)d_in[4];
    const float* Woff = (const float*)d_in[5];
    const float* boff = (const float*)d_in[6];
    const float* Wattn= (const float*)d_in[7];
    const float* battn= (const float*)d_in[8];
    const float* Wout = (const float*)d_in[9];
    const float* bout = (const float*)d_in[10];
    const float* g1   = (const float*)d_in[11];
    const float* b1   = (const float*)d_in[12];
    const float* Wff1 = (const float*)d_in[13];
    const float* bff1 = (const float*)d_in[14];
    const float* Wff2 = (const float*)d_in[15];
    const float* bff2 = (const float*)d_in[16];
    const float* g2   = (const float*)d_in[17];
    const float* b2   = (const float*)d_in[18];
    float* out = (float*)d_out;

    float *q, *val, *off, *attn, *samp, *x, *h;
    cudaGetSymbolAddress((void**)&q, g_q);
    cudaGetSymbolAddress((void**)&val, g_value);
    cudaGetSymbolAddress((void**)&off, g_off);
    cudaGetSymbolAddress((void**)&attn, g_attn);
    cudaGetSymbolAddress((void**)&samp, g_samp);
    cudaGetSymbolAddress((void**)&x, g_x);
    cudaGetSymbolAddress((void**)&h, g_h);

    cudaFuncSetAttribute(gemm_tf32<false>,
                         cudaFuncAttributeMaxDynamicSharedMemorySize, GEMM_SMEM_BYTES);
    cudaFuncSetAttribute(gemm_tf32<true>,
                         cudaFuncAttributeMaxDynamicSharedMemorySize, GEMM_SMEM_BYTES);

    const int n = MM * DD;

    // 1. q = src + pos
    add_kernel<<<(n + 255) / 256, 256>>>(src, pos, q, n);

    dim3 blk(256);
    auto grid_for = [](int Mdim, int N) {
        return dim3((N + BN - 1) / BN, (Mdim + BM - 1) / BM);
    };

    // 2. value = src @ Wv + bv
    gemm_tf32<false><<<grid_for(MM, DD), blk, GEMM_SMEM_BYTES>>>(src, Wv, bv, val, MM, DD, DD);
    // 3. off = q @ Woff + boff
    gemm_tf32<false><<<grid_for(MM, 192), blk, GEMM_SMEM_BYTES>>>(q, Woff, boff, off, MM, 192, DD);
    // 4. attn logits = q @ Wattn + battn
    gemm_tf32<false><<<grid_for(MM, 96), blk, GEMM_SMEM_BYTES>>>(q, Wattn, battn, attn, MM, 96, DD);

    // 5. deformable sampling
    deform_kernel<<<MM, dim3(32, 8)>>>(val, refp, off, attn, samp);

    // 6. attn_out = samp @ Wout + bout  (reuse q as tmp)
    gemm_tf32<false><<<grid_for(MM, DD), blk, GEMM_SMEM_BYTES>>>(samp, Wout, bout, q, MM, DD, DD);

    // 7. x = LN(src + attn_out)
    add_ln_kernel<<<MM, 256>>>(src, q, g1, b1, x);

    // 8. hdn = relu(x @ Wff1 + bff1)
    gemm_tf32<true><<<grid_for(MM, DFF), blk, GEMM_SMEM_BYTES>>>(x, Wff1, bff1, h, MM, DFF, DD);

    // 9. ff = hdn @ Wff2 + bff2  (reuse val as tmp)
    gemm_tf32<false><<<grid_for(MM, DD), blk, GEMM_SMEM_BYTES>>>(h, Wff2, bff2, val, MM, DD, DFF);

    // 10. out = LN(x + ff)
    add_ln_kernel<<<MM, 256>>>(x, val, g2, b2, out);
}

// round 4
// speedup vs baseline: 2.0724x; 1.3521x over previous
#include <cuda_runtime.h>
#include <cuda_bf16.h>
#include <cstdint>
#include <math.h>

// Problem constants
#define BB 4
#define LL 13125
#define MM (BB * LL)      // 52500 rows
#define DD 256
#define NH 8
#define HD 32
#define NLV 3
#define NPT 4
#define DFF 1024
#define EPS 1e-5f

__device__ __constant__ int c_H[NLV] = {100, 50, 25};
__device__ __constant__ int c_W[NLV] = {100, 50, 25};
__device__ __constant__ int c_start[NLV] = {0, 10000, 12500};

// ---------------- scratch ----------------
__device__ float g_q[MM * DD];
__device__ float g_value[MM * DD];
__device__ float g_off[MM * 192];
__device__ float g_attn[MM * 96];
__device__ float g_samp[MM * DD];
__device__ float g_x[MM * DD];
__device__ float g_h[MM * DFF];

// ---------------- elementwise add ----------------
__global__ void add_kernel(const float* __restrict__ a, const float* __restrict__ b,
                           float* __restrict__ out, int n) {
    int i = blockIdx.x * blockDim.x + threadIdx.x;
    if (i < n) out[i] = a[i] + b[i];
}

// ================= TF32 tensor-core GEMM =================
#define BM 128
#define BN 128
#define BK 32
#define A_STRIDE 36
#define B_STRIDE 132
#define ASZ (BM * A_STRIDE)
#define BSZ (BK * B_STRIDE)
#define GEMM_SMEM_BYTES (2 * (ASZ + BSZ) * 4)

__device__ __forceinline__ void cp_async16(void* smem_ptr, const void* gmem_ptr, bool valid) {
    uint32_t saddr = (uint32_t)__cvta_generic_to_shared(smem_ptr);
    int sz = valid ? 16 : 0;
    asm volatile("cp.async.cg.shared.global [%0], [%1], 16, %2;\n"
                 :: "r"(saddr), "l"(gmem_ptr), "r"(sz));
}
__device__ __forceinline__ void cp_commit() {
    asm volatile("cp.async.commit_group;\n");
}
template <int N>
__device__ __forceinline__ void cp_wait() {
    asm volatile("cp.async.wait_group %0;\n" :: "n"(N));
}
__device__ __forceinline__ uint32_t f2tf32(float v) {
    uint32_t r;
    asm("cvt.rna.tf32.f32 %0, %1;\n" : "=r"(r) : "f"(v));
    return r;
}

template <bool RELU>
__global__ void __launch_bounds__(256, 2)
gemm_tf32(const float* __restrict__ A, const float* __restrict__ W,
          const float* __restrict__ bias, float* __restrict__ C,
          int Mdim, int N, int K) {
    extern __shared__ float sm[];
    float* As[2] = { sm, sm + ASZ };
    float* Bs[2] = { sm + 2 * ASZ, sm + 2 * ASZ + BSZ };

    const int tid = threadIdx.x;
    const int lane = tid & 31;
    const int wid = tid >> 5;
    const int warpM = wid & 1;
    const int warpN = wid >> 1;
    const int g = lane >> 2;
    const int t4 = lane & 3;

    const int bm = blockIdx.y * BM;
    const int bn = blockIdx.x * BN;

    const int a_row = tid >> 1;
    const int a_col0 = (tid & 1) * 16;
    const int b_krow = tid >> 3;
    const int b_col0 = (tid & 7) * 16;

    const bool a_row_ok = (bm + a_row) < Mdim;
    const int a_grow = a_row_ok ? (bm + a_row) : 0;

    float acc[4][4][4];
#pragma unroll
    for (int i = 0; i < 4; i++)
#pragma unroll
        for (int j = 0; j < 4; j++)
#pragma unroll
            for (int r = 0; r < 4; r++) acc[i][j][r] = 0.f;

    const int KT = K / BK;

    {
        const float* ag = A + (size_t)a_grow * K + a_col0;
#pragma unroll
        for (int i = 0; i < 4; i++)
            cp_async16(&As[0][a_row * A_STRIDE + a_col0 + 4 * i], ag + 4 * i, a_row_ok);
        const float* bg = W + (size_t)b_krow * N + bn + b_col0;
#pragma unroll
        for (int i = 0; i < 4; i++)
            cp_async16(&Bs[0][b_krow * B_STRIDE + b_col0 + 4 * i], bg + 4 * i,
                       (bn + b_col0 + 4 * i) < N);
        cp_commit();
    }

    for (int kt = 0; kt < KT; kt++) {
        if (kt + 1 < KT) {
            const int k0 = (kt + 1) * BK;
            const int s = (kt + 1) & 1;
            const float* ag = A + (size_t)a_grow * K + k0 + a_col0;
#pragma unroll
            for (int i = 0; i < 4; i++)
                cp_async16(&As[s][a_row * A_STRIDE + a_col0 + 4 * i], ag + 4 * i, a_row_ok);
            const float* bg = W + (size_t)(k0 + b_krow) * N + bn + b_col0;
#pragma unroll
            for (int i = 0; i < 4; i++)
                cp_async16(&Bs[s][b_krow * B_STRIDE + b_col0 + 4 * i], bg + 4 * i,
                           (bn + b_col0 + 4 * i) < N);
            cp_commit();
            cp_wait<1>();
        } else {
            cp_wait<0>();
        }
        __syncthreads();

        const float* Asm = As[kt & 1];
        const float* Bsm = Bs[kt & 1];

#pragma unroll
        for (int ks = 0; ks < 4; ks++) {
            const int k = ks * 8;
            uint32_t af[4][4];
#pragma unroll
            for (int mt = 0; mt < 4; mt++) {
                const int row = warpM * 64 + mt * 16;
                af[mt][0] = f2tf32(Asm[(row + g) * A_STRIDE + k + t4]);
                af[mt][1] = f2tf32(Asm[(row + g + 8) * A_STRIDE + k + t4]);
                af[mt][2] = f2tf32(Asm[(row + g) * A_STRIDE + k + t4 + 4]);
                af[mt][3] = f2tf32(Asm[(row + g + 8) * A_STRIDE + k + t4 + 4]);
            }
            uint32_t bf[4][2];
#pragma unroll
            for (int nt = 0; nt < 4; nt++) {
                const int col = warpN * 32 + nt * 8 + g;
                bf[nt][0] = f2tf32(Bsm[(k + t4) * B_STRIDE + col]);
                bf[nt][1] = f2tf32(Bsm[(k + t4 + 4) * B_STRIDE + col]);
            }
#pragma unroll
            for (int mt = 0; mt < 4; mt++)
#pragma unroll
                for (int nt = 0; nt < 4; nt++) {
                    asm volatile(
                        "mma.sync.aligned.m16n8k8.row.col.f32.tf32.tf32.f32 "
                        "{%0,%1,%2,%3}, {%4,%5,%6,%7}, {%8,%9}, {%0,%1,%2,%3};\n"
                        : "+f"(acc[mt][nt][0]), "+f"(acc[mt][nt][1]),
                          "+f"(acc[mt][nt][2]), "+f"(acc[mt][nt][3])
                        : "r"(af[mt][0]), "r"(af[mt][1]), "r"(af[mt][2]), "r"(af[mt][3]),
                          "r"(bf[nt][0]), "r"(bf[nt][1]));
                }
        }
        __syncthreads();
    }

#pragma unroll
    for (int mt = 0; mt < 4; mt++) {
        const int row0 = bm + warpM * 64 + mt * 16 + g;
#pragma unroll
        for (int nt = 0; nt < 4; nt++) {
            const int col0 = bn + warpN * 32 + nt * 8 + 2 * t4;
            if (col0 < N) {
                const float bx = bias[col0];
                const float by = bias[col0 + 1];
                if (row0 < Mdim) {
                    float v0 = acc[mt][nt][0] + bx;
                    float v1 = acc[mt][nt][1] + by;
                    if (RELU) { v0 = fmaxf(v0, 0.f); v1 = fmaxf(v1, 0.f); }
                    *(float2*)&C[(size_t)row0 * N + col0] = make_float2(v0, v1);
                }
                if (row0 + 8 < Mdim) {
                    float v2 = acc[mt][nt][2] + bx;
                    float v3 = acc[mt][nt][3] + by;
                    if (RELU) { v2 = fmaxf(v2, 0.f); v3 = fmaxf(v3, 0.f); }
                    *(float2*)&C[(size_t)(row0 + 8) * N + col0] = make_float2(v2, v3);
                }
            }
        }
    }
}

// ---------------- deformable attention core (vectorized) ----------------
// One block per query row; 8 warps = 8 heads.
// Lane mapping: pt = lane>>3 (point-within-level 0..3), cg = lane&7 (float4 channel group).
// Each lane accumulates a float4 over its 3 levels; cross-lane reduce over pt.
__global__ void __launch_bounds__(256)
deform_kernel(const float* __restrict__ value,   // [B,L,NH,HD]
              const float* __restrict__ refp,    // [B,L,NL,2]
              const float* __restrict__ off,     // [M,192]
              const float* __restrict__ logits,  // [M,96]
              float* __restrict__ out) {         // [M,256]
    const int row = blockIdx.x;
    const int h = threadIdx.y;
    const int lane = threadIdx.x;
    const int b = row / LL;

    // softmax over the 12 points of this head
    const float* lg = logits + (size_t)row * 96 + h * 12;
    float lv = (lane < 12) ? lg[lane] : -INFINITY;
    float m = lv;
#pragma unroll
    for (int s = 16; s > 0; s >>= 1) m = fmaxf(m, __shfl_xor_sync(0xffffffffu, m, s));
    float e = (lane < 12) ? __expf(lv - m) : 0.f;
    float ssum = e;
#pragma unroll
    for (int s = 16; s > 0; s >>= 1) ssum += __shfl_xor_sync(0xffffffffu, ssum, s);
    float w12 = e / ssum;

    const float* offrow = off + (size_t)row * 192 + h * 24;
    const float* refrow = refp + (size_t)row * NLV * 2;
    const float4* val4 = (const float4*)value;

    const int pt = lane >> 3;   // 0..3
    const int cg = lane & 7;    // 0..7

    float4 acc = make_float4(0.f, 0.f, 0.f, 0.f);

#pragma unroll
    for (int l = 0; l < NLV; l++) {
        const int Hh = c_H[l], Ww = c_W[l], st = c_start[l];
        const int p = l * NPT + pt;
        const float rx = refrow[l * 2 + 0];
        const float ry = refrow[l * 2 + 1];
        const float ox = offrow[p * 2 + 0];
        const float oy = offrow[p * 2 + 1];
        const float aw = __shfl_sync(0xffffffffu, w12, p);

        float x = (rx + ox / (float)Ww) * (float)Ww - 0.5f;
        float y = (ry + oy / (float)Hh) * (float)Hh - 0.5f;
        float x0f = floorf(x), y0f = floorf(y);
        int x0 = (int)x0f, y0 = (int)y0f;
        int x1 = x0 + 1, y1 = y0 + 1;
        float wx1 = x - x0f, wy1 = y - y0f;
        float wx0 = 1.f - wx1, wy0 = 1.f - wy1;

        bool vx0 = (x0 >= 0) & (x0 < Ww);
        bool vx1 = (x1 >= 0) & (x1 < Ww);
        bool vy0 = (y0 >= 0) & (y0 < Hh);
        bool vy1 = (y1 >= 0) & (y1 < Hh);

        // float4 index: row_index*64 + h*8 + cg
        const size_t base = ((size_t)(b * LL + st)) * 64 + h * 8 + cg;
        float4 s00 = make_float4(0,0,0,0), s10 = s00, s01 = s00, s11 = s00;
        if (vx0 & vy0) s00 = val4[base + (size_t)(y0 * Ww + x0) * 64];
        if (vx1 & vy0) s10 = val4[base + (size_t)(y0 * Ww + x1) * 64];
        if (vx0 & vy1) s01 = val4[base + (size_t)(y1 * Ww + x0) * 64];
        if (vx1 & vy1) s11 = val4[base + (size_t)(y1 * Ww + x1) * 64];

        const float w00 = wx0 * wy0 * aw, w10 = wx1 * wy0 * aw;
        const float w01 = wx0 * wy1 * aw, w11 = wx1 * wy1 * aw;
        acc.x += s00.x * w00 + s10.x * w10 + s01.x * w01 + s11.x * w11;
        acc.y += s00.y * w00 + s10.y * w10 + s01.y * w01 + s11.y * w11;
        acc.z += s00.z * w00 + s10.z * w10 + s01.z * w01 + s11.z * w11;
        acc.w += s00.w * w00 + s10.w * w10 + s01.w * w01 + s11.w * w11;
    }

    // reduce over pt dimension (lanes differing in bits 3,4)
#pragma unroll
    for (int s = 8; s <= 16; s <<= 1) {
        acc.x += __shfl_xor_sync(0xffffffffu, acc.x, s);
        acc.y += __shfl_xor_sync(0xffffffffu, acc.y, s);
        acc.z += __shfl_xor_sync(0xffffffffu, acc.z, s);
        acc.w += __shfl_xor_sync(0xffffffffu, acc.w, s);
    }
    if (pt == 0) {
        ((float4*)out)[(size_t)row * 64 + h * 8 + cg] = acc;
    }
}

// ---------------- fused add + LayerNorm ----------------
__global__ void __launch_bounds__(256)
add_ln_kernel(const float* __restrict__ a, const float* __restrict__ b,
              const float* __restrict__ gamma, const float* __restrict__ beta,
              float* __restrict__ out) {
    const int row = blockIdx.x;
    const int t = threadIdx.x;
    float v = a[(size_t)row * DD + t] + b[(size_t)row * DD + t];

    float s = v, sq = v * v;
#pragma unroll
    for (int d = 16; d > 0; d >>= 1) {
        s += __shfl_xor_sync(0xffffffffu, s, d);
        sq += __shfl_xor_sync(0xffffffffu, sq, d);
    }
    __shared__ float ws[8], wsq[8];
    int wid = t >> 5, lane = t & 31;
    if (lane == 0) { ws[wid] = s; wsq[wid] = sq; }
    __syncthreads();
    if (t < 32) {
        float s2 = (t < 8) ? ws[t] : 0.f;
        float sq2 = (t < 8) ? wsq[t] : 0.f;
#pragma unroll
        for (int d = 4; d > 0; d >>= 1) {
            s2 += __shfl_xor_sync(0xffffffffu, s2, d);
            sq2 += __shfl_xor_sync(0xffffffffu, sq2, d);
        }
        if (t == 0) { ws[0] = s2; wsq[0] = sq2; }
    }
    __syncthreads();
    float mean = ws[0] * (1.f / DD);
    float var = wsq[0] * (1.f / DD) - mean * mean;
    float inv = rsqrtf(var + EPS);
    out[(size_t)row * DD + t] = (v - mean) * inv * gamma[t] + beta[t];
}

// ---------------- launch ----------------
extern "C" void kernel_launch(void* const* d_in, const int* in_sizes, int n_in,
                              void* d_out, int out_size) {
    const float* src  = (const float*)d_in[0];
    const float* pos  = (const float*)d_in[1];
    const float* refp = (const float*)d_in[2];
    const float* Wv   = (const float*)d_in[3];
    const float* bv   = (const float*)d_in[4];
    const float* Woff = (const float*)d_in[5];
    const float* boff = (const float*)d_in[6];
    const float* Wattn= (const float*)d_in[7];
    const float* battn= (const float*)d_in[8];
    const float* Wout = (const float*)d_in[9];
    const float* bout = (const float*)d_in[10];
    const float* g1   = (const float*)d_in[11];
    const float* b1   = (const float*)d_in[12];
    const float* Wff1 = (const float*)d_in[13];
    const float* bff1 = (const float*)d_in[14];
    const float* Wff2 = (const float*)d_in[15];
    const float* bff2 = (const float*)d_in[16];
    const float* g2   = (const float*)d_in[17];
    const float* b2   = (const float*)d_in[18];
    float* out = (float*)d_out;

    float *q, *val, *off, *attn, *samp, *x, *h;
    cudaGetSymbolAddress((void**)&q, g_q);
    cudaGetSymbolAddress((void**)&val, g_value);
    cudaGetSymbolAddress((void**)&off, g_off);
    cudaGetSymbolAddress((void**)&attn, g_attn);
    cudaGetSymbolAddress((void**)&samp, g_samp);
    cudaGetSymbolAddress((void**)&x, g_x);
    cudaGetSymbolAddress((void**)&h, g_h);

    cudaFuncSetAttribute(gemm_tf32<false>,
                         cudaFuncAttributeMaxDynamicSharedMemorySize, GEMM_SMEM_BYTES);
    cudaFuncSetAttribute(gemm_tf32<true>,
                         cudaFuncAttributeMaxDynamicSharedMemorySize, GEMM_SMEM_BYTES);

    const int n = MM * DD;

    add_kernel<<<(n + 255) / 256, 256>>>(src, pos, q, n);

    dim3 blk(256);
    auto grid_for = [](int Mdim, int N) {
        return dim3((N + BN - 1) / BN, (Mdim + BM - 1) / BM);
    };

    gemm_tf32<false><<<grid_for(MM, DD), blk, GEMM_SMEM_BYTES>>>(src, Wv, bv, val, MM, DD, DD);
    gemm_tf32<false><<<grid_for(MM, 192), blk, GEMM_SMEM_BYTES>>>(q, Woff, boff, off, MM, 192, DD);
    gemm_tf32<false><<<grid_for(MM, 96), blk, GEMM_SMEM_BYTES>>>(q, Wattn, battn, attn, MM, 96, DD);

    deform_kernel<<<MM, dim3(32, 8)>>>(val, refp, off, attn, samp);

    gemm_tf32<false><<<grid_for(MM, DD), blk, GEMM_SMEM_BYTES>>>(samp, Wout, bout, q, MM, DD, DD);

    add_ln_kernel<<<MM, 256>>>(src, q, g1, b1, x);

    gemm_tf32<true><<<grid_for(MM, DFF), blk, GEMM_SMEM_BYTES>>>(x, Wff1, bff1, h, MM, DFF, DD);

    gemm_tf32<false><<<grid_for(MM, DD), blk, GEMM_SMEM_BYTES>>>(h, Wff2, bff2, val, MM, DD, DFF);

    add_ln_kernel<<<MM, 256>>>(x, val, g2, b2, out);
}

// round 5
// speedup vs baseline: 3.3940x; 1.6377x over previous
#include <cuda_runtime.h>
#include <cuda_fp16.h>
#include <cstdint>
#include <math.h>

// Problem constants
#define BB 4
#define LL 13125
#define MM (BB * LL)      // 52500 rows
#define DD 256
#define NH 8
#define HD 32
#define NLV 3
#define NPT 4
#define DFF 1024
#define EPS 1e-5f

__device__ __constant__ int c_H[NLV] = {100, 50, 25};
__device__ __constant__ int c_W[NLV] = {100, 50, 25};
__device__ __constant__ int c_start[NLV] = {0, 10000, 12500};

// ---------------- scratch ----------------
__device__ __half g_qh[MM * DD];
__device__ __half g_srch[MM * DD];
__device__ float  g_value[MM * DD];
__device__ float  g_off[MM * 192];
__device__ float  g_attn[MM * 96];
__device__ __half g_samph[MM * DD];
__device__ float  g_x[MM * DD];
__device__ __half g_xh[MM * DD];
__device__ __half g_hh[MM * DFF];
__device__ float  g_tmp[MM * DD];
// fp16 transposed weights [N][K]
__device__ __half g_wvT[DD * DD];
__device__ __half g_woffT[192 * DD];
__device__ __half g_wattnT[96 * DD];
__device__ __half g_woutT[DD * DD];
__device__ __half g_wff1T[DFF * DD];
__device__ __half g_wff2T[DD * DFF];

// ---------------- weight convert + transpose ----------------
__global__ void cvt_wT(const float* __restrict__ W, __half* __restrict__ Wt, int K, int N) {
    int idx = blockIdx.x * blockDim.x + threadIdx.x;
    if (idx < K * N) {
        int k = idx / N, n = idx % N;
        Wt[(size_t)n * K + k] = __float2half(W[idx]);
    }
}

// ---------------- fused q = src+pos (fp16) and src->fp16 ----------------
__global__ void add_cvt_kernel(const float* __restrict__ src, const float* __restrict__ pos,
                               __half* __restrict__ qh, __half* __restrict__ srch, int n) {
    int i = blockIdx.x * blockDim.x + threadIdx.x;
    if (i < n) {
        float s = src[i];
        qh[i] = __float2half(s + pos[i]);
        srch[i] = __float2half(s);
    }
}

// ================= FP16 tensor-core GEMM =================
// C[M,N] = A[M,K] @ W[K,N] + bias. Weights supplied transposed fp16 [N][K].
// MMA roles swapped: A-operand = weight tile (m = weight col), B-operand = act tile (n = act row).
// Block tile: 128 act rows x 128 weight cols, BK=32. 8 warps: warpA (4) x warpW (2).
// Warp tile: 32 act rows x 64 weight cols = 4 nt x 4 mt of m16n8k16.

#define BK 32
#define KPAD 40   // halves per smem row (pad for conflict-free LDS)

__device__ __forceinline__ void cp_async16(void* smem_ptr, const void* gmem_ptr, bool valid) {
    uint32_t saddr = (uint32_t)__cvta_generic_to_shared(smem_ptr);
    int sz = valid ? 16 : 0;
    asm volatile("cp.async.cg.shared.global [%0], [%1], 16, %2;\n"
                 :: "r"(saddr), "l"(gmem_ptr), "r"(sz));
}
__device__ __forceinline__ void cp_commit() {
    asm volatile("cp.async.commit_group;\n");
}
template <int N>
__device__ __forceinline__ void cp_wait() {
    asm volatile("cp.async.wait_group %0;\n" :: "n"(N));
}

template <bool RELU, bool HALF_OUT>
__global__ void __launch_bounds__(256, 2)
gemm_f16(const __half* __restrict__ Aact,  // [Mdim][K]
         const __half* __restrict__ Wt,    // [N][K]
         const float* __restrict__ bias,
         float* __restrict__ C,            // [Mdim][N] if !HALF_OUT
         __half* __restrict__ Ch,          // [Mdim][N] if HALF_OUT
         int Mdim, int N, int K) {
    __shared__ __half As[2][128 * KPAD];   // act tile  [actrow][k]
    __shared__ __half Ws[2][128 * KPAD];   // weight tile [wcol][k]

    const int tid = threadIdx.x;
    const int lane = tid & 31;
    const int wid = tid >> 5;
    const int warpW = wid & 1;    // 0..1 over weight cols (64 each)
    const int warpA = wid >> 1;   // 0..3 over act rows (32 each)
    const int g = lane >> 2;      // 0..7
    const int t4 = lane & 3;      // 0..3

    const int bm = blockIdx.y * 128;   // act rows
    const int bn = blockIdx.x * 128;   // weight cols

    // load mapping: 2 chunks of 16B per thread per tile
    const int l_row = tid >> 1;            // 0..127
    const int l_kc0 = (tid & 1) * 2;       // chunk index 0 or 2 (chunk = 8 halves)

    const bool a_ok = (bm + l_row) < Mdim;
    const bool w_ok = (bn + l_row) < N;

    float acc[4][4][4];
#pragma unroll
    for (int i = 0; i < 4; i++)
#pragma unroll
        for (int j = 0; j < 4; j++)
#pragma unroll
            for (int r = 0; r < 4; r++) acc[i][j][r] = 0.f;

    const int KT = K / BK;

    // prologue
    {
        const __half* ag = Aact + (size_t)(bm + l_row) * K + l_kc0 * 8;
        const __half* wg = Wt + (size_t)(bn + l_row) * K + l_kc0 * 8;
#pragma unroll
        for (int i = 0; i < 2; i++) {
            cp_async16(&As[0][l_row * KPAD + (l_kc0 + i) * 8], ag + i * 8, a_ok);
            cp_async16(&Ws[0][l_row * KPAD + (l_kc0 + i) * 8], wg + i * 8, w_ok);
        }
        cp_commit();
    }

    for (int kt = 0; kt < KT; kt++) {
        if (kt + 1 < KT) {
            const int k0 = (kt + 1) * BK;
            const int s = (kt + 1) & 1;
            const __half* ag = Aact + (size_t)(bm + l_row) * K + k0 + l_kc0 * 8;
            const __half* wg = Wt + (size_t)(bn + l_row) * K + k0 + l_kc0 * 8;
#pragma unroll
            for (int i = 0; i < 2; i++) {
                cp_async16(&As[s][l_row * KPAD + (l_kc0 + i) * 8], ag + i * 8, a_ok);
                cp_async16(&Ws[s][l_row * KPAD + (l_kc0 + i) * 8], wg + i * 8, w_ok);
            }
            cp_commit();
            cp_wait<1>();
        } else {
            cp_wait<0>();
        }
        __syncthreads();

        const __half* Asm = As[kt & 1];
        const __half* Wsm = Ws[kt & 1];

#pragma unroll
        for (int ks = 0; ks < 2; ks++) {
            const int kb = ks * 16;
            // B fragments (activations): act row = warpA*32 + nt*8 + g, k = kb + 2*t4 (+8)
            uint32_t bfr[4][2];
#pragma unroll
            for (int nt = 0; nt < 4; nt++) {
                const __half* p = &Asm[(warpA * 32 + nt * 8 + g) * KPAD + kb + 2 * t4];
                bfr[nt][0] = *(const uint32_t*)p;
                bfr[nt][1] = *(const uint32_t*)(p + 8);
            }
            // A fragments (weights): weight col = warpW*64 + mt*16 + g (+8), k = kb + 2*t4 (+8)
            uint32_t afr[4][4];
#pragma unroll
            for (int mt = 0; mt < 4; mt++) {
                const __half* p = &Wsm[(warpW * 64 + mt * 16 + g) * KPAD + kb + 2 * t4];
                afr[mt][0] = *(const uint32_t*)p;
                afr[mt][1] = *(const uint32_t*)(p + 8 * KPAD);
                afr[mt][2] = *(const uint32_t*)(p + 8);
                afr[mt][3] = *(const uint32_t*)(p + 8 * KPAD + 8);
            }
#pragma unroll
            for (int mt = 0; mt < 4; mt++)
#pragma unroll
                for (int nt = 0; nt < 4; nt++) {
                    asm volatile(
                        "mma.sync.aligned.m16n8k16.row.col.f32.f16.f16.f32 "
                        "{%0,%1,%2,%3}, {%4,%5,%6,%7}, {%8,%9}, {%0,%1,%2,%3};\n"
                        : "+f"(acc[mt][nt][0]), "+f"(acc[mt][nt][1]),
                          "+f"(acc[mt][nt][2]), "+f"(acc[mt][nt][3])
                        : "r"(afr[mt][0]), "r"(afr[mt][1]), "r"(afr[mt][2]), "r"(afr[mt][3]),
                          "r"(bfr[nt][0]), "r"(bfr[nt][1]));
                }
        }
        __syncthreads();
    }

    // epilogue: D[m=weight col][n=act row] -> C[act_row][weight_col]
#pragma unroll
    for (int mt = 0; mt < 4; mt++) {
        const int wc = bn + warpW * 64 + mt * 16 + g;
        const bool c0ok = wc < N;
        const bool c8ok = (wc + 8) < N;
        const float b0 = c0ok ? bias[wc] : 0.f;
        const float b8 = c8ok ? bias[wc + 8] : 0.f;
#pragma unroll
        for (int nt = 0; nt < 4; nt++) {
            const int ar = bm + warpA * 32 + nt * 8 + 2 * t4;
#pragma unroll
            for (int half_i = 0; half_i < 2; half_i++) {
                const int r = ar + half_i;
                if (r >= Mdim) continue;
                float v0 = acc[mt][nt][0 + half_i] + b0;
                float v8 = acc[mt][nt][2 + half_i] + b8;
                if (RELU) { v0 = fmaxf(v0, 0.f); v8 = fmaxf(v8, 0.f); }
                if (HALF_OUT) {
                    if (c0ok) Ch[(size_t)r * N + wc] = __float2half(v0);
                    if (c8ok) Ch[(size_t)r * N + wc + 8] = __float2half(v8);
                } else {
                    if (c0ok) C[(size_t)r * N + wc] = v0;
                    if (c8ok) C[(size_t)r * N + wc + 8] = v8;
                }
            }
        }
    }
}

// ---------------- deformable attention core (vectorized, fp16 out) ----------------
__global__ void __launch_bounds__(256)
deform_kernel(const float* __restrict__ value,   // [B,L,NH,HD] fp32
              const float* __restrict__ refp,    // [B,L,NL,2]
              const float* __restrict__ off,     // [M,192]
              const float* __restrict__ logits,  // [M,96]
              __half* __restrict__ outh) {       // [M,256] fp16
    const int row = blockIdx.x;
    const int h = threadIdx.y;
    const int lane = threadIdx.x;
    const int b = row / LL;

    const float* lg = logits + (size_t)row * 96 + h * 12;
    float lv = (lane < 12) ? lg[lane] : -INFINITY;
    float m = lv;
#pragma unroll
    for (int s = 16; s > 0; s >>= 1) m = fmaxf(m, __shfl_xor_sync(0xffffffffu, m, s));
    float e = (lane < 12) ? __expf(lv - m) : 0.f;
    float ssum = e;
#pragma unroll
    for (int s = 16; s > 0; s >>= 1) ssum += __shfl_xor_sync(0xffffffffu, ssum, s);
    float w12 = e / ssum;

    const float* offrow = off + (size_t)row * 192 + h * 24;
    const float* refrow = refp + (size_t)row * NLV * 2;
    const float4* val4 = (const float4*)value;

    const int pt = lane >> 3;   // 0..3
    const int cg = lane & 7;    // 0..7

    float4 acc = make_float4(0.f, 0.f, 0.f, 0.f);

#pragma unroll
    for (int l = 0; l < NLV; l++) {
        const int Hh = c_H[l], Ww = c_W[l], st = c_start[l];
        const int p = l * NPT + pt;
        const float rx = refrow[l * 2 + 0];
        const float ry = refrow[l * 2 + 1];
        const float ox = offrow[p * 2 + 0];
        const float oy = offrow[p * 2 + 1];
        const float aw = __shfl_sync(0xffffffffu, w12, p);

        float x = (rx + ox / (float)Ww) * (float)Ww - 0.5f;
        float y = (ry + oy / (float)Hh) * (float)Hh - 0.5f;
        float x0f = floorf(x), y0f = floorf(y);
        int x0 = (int)x0f, y0 = (int)y0f;
        int x1 = x0 + 1, y1 = y0 + 1;
        float wx1 = x - x0f, wy1 = y - y0f;
        float wx0 = 1.f - wx1, wy0 = 1.f - wy1;

        bool vx0 = (x0 >= 0) & (x0 < Ww);
        bool vx1 = (x1 >= 0) & (x1 < Ww);
        bool vy0 = (y0 >= 0) & (y0 < Hh);
        bool vy1 = (y1 >= 0) & (y1 < Hh);

        const size_t base = ((size_t)(b * LL + st)) * 64 + h * 8 + cg;
        float4 s00 = make_float4(0,0,0,0), s10 = s00, s01 = s00, s11 = s00;
        if (vx0 & vy0) s00 = val4[base + (size_t)(y0 * Ww + x0) * 64];
        if (vx1 & vy0) s10 = val4[base + (size_t)(y0 * Ww + x1) * 64];
        if (vx0 & vy1) s01 = val4[base + (size_t)(y1 * Ww + x0) * 64];
        if (vx1 & vy1) s11 = val4[base + (size_t)(y1 * Ww + x1) * 64];

        const float w00 = wx0 * wy0 * aw, w10 = wx1 * wy0 * aw;
        const float w01 = wx0 * wy1 * aw, w11 = wx1 * wy1 * aw;
        acc.x += s00.x * w00 + s10.x * w10 + s01.x * w01 + s11.x * w11;
        acc.y += s00.y * w00 + s10.y * w10 + s01.y * w01 + s11.y * w11;
        acc.z += s00.z * w00 + s10.z * w10 + s01.z * w01 + s11.z * w11;
        acc.w += s00.w * w00 + s10.w * w10 + s01.w * w01 + s11.w * w11;
    }

#pragma unroll
    for (int s = 8; s <= 16; s <<= 1) {
        acc.x += __shfl_xor_sync(0xffffffffu, acc.x, s);
        acc.y += __shfl_xor_sync(0xffffffffu, acc.y, s);
        acc.z += __shfl_xor_sync(0xffffffffu, acc.z, s);
        acc.w += __shfl_xor_sync(0xffffffffu, acc.w, s);
    }
    if (pt == 0) {
        __half2 h01 = __floats2half2_rn(acc.x, acc.y);
        __half2 h23 = __floats2half2_rn(acc.z, acc.w);
        __half2* dst = (__half2*)(outh + (size_t)row * DD + h * 32 + cg * 4);
        dst[0] = h01;
        dst[1] = h23;
    }
}

// ---------------- fused add + LayerNorm (fp32 out + optional fp16 out) ----------------
__global__ void __launch_bounds__(256)
add_ln_kernel(const float* __restrict__ a, const float* __restrict__ b,
              const float* __restrict__ gamma, const float* __restrict__ beta,
              float* __restrict__ out, __half* __restrict__ outh) {
    const int row = blockIdx.x;
    const int t = threadIdx.x;
    float v = a[(size_t)row * DD + t] + b[(size_t)row * DD + t];

    float s = v, sq = v * v;
#pragma unroll
    for (int d = 16; d > 0; d >>= 1) {
        s += __shfl_xor_sync(0xffffffffu, s, d);
        sq += __shfl_xor_sync(0xffffffffu, sq, d);
    }
    __shared__ float ws[8], wsq[8];
    int wid = t >> 5, lane = t & 31;
    if (lane == 0) { ws[wid] = s; wsq[wid] = sq; }
    __syncthreads();
    if (t < 32) {
        float s2 = (t < 8) ? ws[t] : 0.f;
        float sq2 = (t < 8) ? wsq[t] : 0.f;
#pragma unroll
        for (int d = 4; d > 0; d >>= 1) {
            s2 += __shfl_xor_sync(0xffffffffu, s2, d);
            sq2 += __shfl_xor_sync(0xffffffffu, sq2, d);
        }
        if (t == 0) { ws[0] = s2; wsq[0] = sq2; }
    }
    __syncthreads();
    float mean = ws[0] * (1.f / DD);
    float var = wsq[0] * (1.f / DD) - mean * mean;
    float inv = rsqrtf(var + EPS);
    float r = (v - mean) * inv * gamma[t] + beta[t];
    out[(size_t)row * DD + t] = r;
    if (outh) outh[(size_t)row * DD + t] = __float2half(r);
}

// ---------------- launch ----------------
extern "C" void kernel_launch(void* const* d_in, const int* in_sizes, int n_in,
                              void* d_out, int out_size) {
    const float* src  = (const float*)d_in[0];
    const float* pos  = (const float*)d_in[1];
    const float* refp = (const float*)d_in[2];
    const float* Wv   = (const float*)d_in[3];
    const float* bv   = (const float*)d_in[4];
    const float* Woff = (const float*)d_in[5];
    const float* boff = (const float*)d_in[6];
    const float* Wattn= (const float*)d_in[7];
    const float* battn= (const float*)d_in[8];
    const float* Wout = (const float*)d_in[9];
    const float* bout = (const float*)d_in[10];
    const float* g1   = (const float*)d_in[11];
    const float* b1   = (const float*)d_in[12];
    const float* Wff1 = (const float*)d_in[13];
    const float* bff1 = (const float*)d_in[14];
    const float* Wff2 = (const float*)d_in[15];
    const float* bff2 = (const float*)d_in[16];
    const float* g2   = (const float*)d_in[17];
    const float* b2   = (const float*)d_in[18];
    float* out = (float*)d_out;

    __half *qh, *srch, *samph, *xh, *hh;
    __half *wvT, *woffT, *wattnT, *woutT, *wff1T, *wff2T;
    float *val, *off, *attn, *x, *tmp;
    cudaGetSymbolAddress((void**)&qh, g_qh);
    cudaGetSymbolAddress((void**)&srch, g_srch);
    cudaGetSymbolAddress((void**)&val, g_value);
    cudaGetSymbolAddress((void**)&off, g_off);
    cudaGetSymbolAddress((void**)&attn, g_attn);
    cudaGetSymbolAddress((void**)&samph, g_samph);
    cudaGetSymbolAddress((void**)&x, g_x);
    cudaGetSymbolAddress((void**)&xh, g_xh);
    cudaGetSymbolAddress((void**)&hh, g_hh);
    cudaGetSymbolAddress((void**)&tmp, g_tmp);
    cudaGetSymbolAddress((void**)&wvT, g_wvT);
    cudaGetSymbolAddress((void**)&woffT, g_woffT);
    cudaGetSymbolAddress((void**)&wattnT, g_wattnT);
    cudaGetSymbolAddress((void**)&woutT, g_woutT);
    cudaGetSymbolAddress((void**)&wff1T, g_wff1T);
    cudaGetSymbolAddress((void**)&wff2T, g_wff2T);

    // weight conversions (tiny)
    cvt_wT<<<(DD * DD + 255) / 256, 256>>>(Wv, wvT, DD, DD);
    cvt_wT<<<(DD * 192 + 255) / 256, 256>>>(Woff, woffT, DD, 192);
    cvt_wT<<<(DD * 96 + 255) / 256, 256>>>(Wattn, wattnT, DD, 96);
    cvt_wT<<<(DD * DD + 255) / 256, 256>>>(Wout, woutT, DD, DD);
    cvt_wT<<<(DD * DFF + 255) / 256, 256>>>(Wff1, wff1T, DD, DFF);
    cvt_wT<<<(DFF * DD + 255) / 256, 256>>>(Wff2, wff2T, DFF, DD);

    const int n = MM * DD;
    add_cvt_kernel<<<(n + 255) / 256, 256>>>(src, pos, qh, srch, n);

    dim3 blk(256);
    auto grid_for = [](int Mdim, int N) {
        return dim3((N + 127) / 128, (Mdim + 127) / 128);
    };

    // value = src @ Wv + bv (fp32 out, feeds deform)
    gemm_f16<false, false><<<grid_for(MM, DD), blk>>>(srch, wvT, bv, val, nullptr, MM, DD, DD);
    // off = q @ Woff + boff
    gemm_f16<false, false><<<grid_for(MM, 192), blk>>>(qh, woffT, boff, off, nullptr, MM, 192, DD);
    // attn logits = q @ Wattn + battn
    gemm_f16<false, false><<<grid_for(MM, 96), blk>>>(qh, wattnT, battn, attn, nullptr, MM, 96, DD);

    // deformable sampling -> samp (fp16)
    deform_kernel<<<MM, dim3(32, 8)>>>(val, refp, off, attn, samph);

    // attn_out = samp @ Wout + bout (fp32 tmp)
    gemm_f16<false, false><<<grid_for(MM, DD), blk>>>(samph, woutT, bout, tmp, nullptr, MM, DD, DD);

    // x = LN(src + attn_out) -> fp32 + fp16
    add_ln_kernel<<<MM, 256>>>(src, tmp, g1, b1, x, xh);

    // h = relu(x @ Wff1 + bff1) (fp16 out)
    gemm_f16<true, true><<<grid_for(MM, DFF), blk>>>(xh, wff1T, bff1, nullptr, hh, MM, DFF, DD);

    // ff = h @ Wff2 + bff2 (fp32 tmp)
    gemm_f16<false, false><<<grid_for(MM, DD), blk>>>(hh, wff2T, bff2, tmp, nullptr, MM, DD, DFF);

    // out = LN(x + ff)
    add_ln_kernel<<<MM, 256>>>(x, tmp, g2, b2, out, nullptr);
}

// round 6
// speedup vs baseline: 3.5068x; 1.0332x over previous
#include <cuda_runtime.h>
#include <cuda_fp16.h>
#include <cstdint>
#include <math.h>

// Problem constants
#define BB 4
#define LL 13125
#define MM (BB * LL)      // 52500 rows
#define DD 256
#define NH 8
#define HD 32
#define NLV 3
#define NPT 4
#define DFF 1024
#define EPS 1e-5f

__device__ __constant__ int c_H[NLV] = {100, 50, 25};
__device__ __constant__ int c_W[NLV] = {100, 50, 25};
__device__ __constant__ int c_start[NLV] = {0, 10000, 12500};

// ---------------- scratch ----------------
__device__ __half g_qh[MM * DD];
__device__ __half g_srch[MM * DD];
__device__ __half g_valh[MM * DD];
__device__ float  g_offattn[MM * 288];   // cols 0..191 = off, 192..287 = attn logits
__device__ __half g_samph[MM * DD];
__device__ float  g_x[MM * DD];
__device__ __half g_xh[MM * DD];
__device__ __half g_hh[MM * DFF];
__device__ float  g_tmp[MM * DD];
// fp16 transposed weights [N][K]
__device__ __half g_wvT[DD * DD];
__device__ __half g_woaT[288 * DD];      // combined Woff|Wattn transposed
__device__ __half g_woutT[DD * DD];
__device__ __half g_wff1T[DFF * DD];
__device__ __half g_wff2T[DD * DFF];
__device__ float  g_boa[288];            // combined boff|battn

// ---------------- fused weight convert/transpose + bias concat ----------------
#define CV0 (DD*DD)              // Wv
#define CV1 (CV0 + DD*192)       // Woff
#define CV2 (CV1 + DD*96)        // Wattn
#define CV3 (CV2 + DD*DD)        // Wout
#define CV4 (CV3 + DD*DFF)       // Wff1
#define CV5 (CV4 + DFF*DD)       // Wff2
#define CVT_TOTAL (CV5 + 288)    // + bias

__global__ void cvt_all(const float* __restrict__ Wv, const float* __restrict__ Woff,
                        const float* __restrict__ Wattn, const float* __restrict__ Wout,
                        const float* __restrict__ Wff1, const float* __restrict__ Wff2,
                        const float* __restrict__ boff, const float* __restrict__ battn) {
    int idx = blockIdx.x * blockDim.x + threadIdx.x;
    if (idx >= CVT_TOTAL) return;
    if (idx < CV0) {
        int k = idx / DD, n = idx % DD;
        g_wvT[(size_t)n * DD + k] = __float2half(Wv[idx]);
    } else if (idx < CV1) {
        int i = idx - CV0;
        int k = i / 192, n = i % 192;
        g_woaT[(size_t)n * DD + k] = __float2half(Woff[i]);
    } else if (idx < CV2) {
        int i = idx - CV1;
        int k = i / 96, n = i % 96;
        g_woaT[(size_t)(192 + n) * DD + k] = __float2half(Wattn[i]);
    } else if (idx < CV3) {
        int i = idx - CV2;
        int k = i / DD, n = i % DD;
        g_woutT[(size_t)n * DD + k] = __float2half(Wout[i]);
    } else if (idx < CV4) {
        int i = idx - CV3;
        int k = i / DFF, n = i % DFF;
        g_wff1T[(size_t)n * DD + k] = __float2half(Wff1[i]);
    } else if (idx < CV5) {
        int i = idx - CV4;
        int k = i / DD, n = i % DD;
        g_wff2T[(size_t)n * DFF + k] = __float2half(Wff2[i]);
    } else {
        int i = idx - CV5;
        g_boa[i] = (i < 192) ? boff[i] : battn[i - 192];
    }
}

// ---------------- fused q = src+pos (fp16) and src->fp16 ----------------
__global__ void add_cvt_kernel(const float* __restrict__ src, const float* __restrict__ pos,
                               __half* __restrict__ qh, __half* __restrict__ srch, int n) {
    int i = blockIdx.x * blockDim.x + threadIdx.x;
    if (i < n) {
        float s = src[i];
        qh[i] = __float2half(s + pos[i]);
        srch[i] = __float2half(s);
    }
}

// ================= FP16 tensor-core GEMM =================
#define BK 32
#define KPAD 40

__device__ __forceinline__ void cp_async16(void* smem_ptr, const void* gmem_ptr, bool valid) {
    uint32_t saddr = (uint32_t)__cvta_generic_to_shared(smem_ptr);
    int sz = valid ? 16 : 0;
    asm volatile("cp.async.cg.shared.global [%0], [%1], 16, %2;\n"
                 :: "r"(saddr), "l"(gmem_ptr), "r"(sz));
}
__device__ __forceinline__ void cp_commit() {
    asm volatile("cp.async.commit_group;\n");
}
template <int N>
__device__ __forceinline__ void cp_wait() {
    asm volatile("cp.async.wait_group %0;\n" :: "n"(N));
}

template <bool RELU, bool HALF_OUT>
__global__ void __launch_bounds__(256, 2)
gemm_f16(const __half* __restrict__ Aact,  // [Mdim][K]
         const __half* __restrict__ Wt,    // [N][K]
         const float* __restrict__ bias,
         float* __restrict__ C,
         __half* __restrict__ Ch,
         int Mdim, int N, int K) {
    __shared__ __half As[2][128 * KPAD];
    __shared__ __half Ws[2][128 * KPAD];

    const int tid = threadIdx.x;
    const int lane = tid & 31;
    const int wid = tid >> 5;
    const int warpW = wid & 1;
    const int warpA = wid >> 1;
    const int g = lane >> 2;
    const int t4 = lane & 3;

    const int bm = blockIdx.y * 128;
    const int bn = blockIdx.x * 128;

    const int l_row = tid >> 1;
    const int l_kc0 = (tid & 1) * 2;

    const bool a_ok = (bm + l_row) < Mdim;
    const bool w_ok = (bn + l_row) < N;

    float acc[4][4][4];
#pragma unroll
    for (int i = 0; i < 4; i++)
#pragma unroll
        for (int j = 0; j < 4; j++)
#pragma unroll
            for (int r = 0; r < 4; r++) acc[i][j][r] = 0.f;

    const int KT = K / BK;

    {
        const __half* ag = Aact + (size_t)(bm + l_row) * K + l_kc0 * 8;
        const __half* wg = Wt + (size_t)(bn + l_row) * K + l_kc0 * 8;
#pragma unroll
        for (int i = 0; i < 2; i++) {
            cp_async16(&As[0][l_row * KPAD + (l_kc0 + i) * 8], ag + i * 8, a_ok);
            cp_async16(&Ws[0][l_row * KPAD + (l_kc0 + i) * 8], wg + i * 8, w_ok);
        }
        cp_commit();
    }

    for (int kt = 0; kt < KT; kt++) {
        if (kt + 1 < KT) {
            const int k0 = (kt + 1) * BK;
            const int s = (kt + 1) & 1;
            const __half* ag = Aact + (size_t)(bm + l_row) * K + k0 + l_kc0 * 8;
            const __half* wg = Wt + (size_t)(bn + l_row) * K + k0 + l_kc0 * 8;
#pragma unroll
            for (int i = 0; i < 2; i++) {
                cp_async16(&As[s][l_row * KPAD + (l_kc0 + i) * 8], ag + i * 8, a_ok);
                cp_async16(&Ws[s][l_row * KPAD + (l_kc0 + i) * 8], wg + i * 8, w_ok);
            }
            cp_commit();
            cp_wait<1>();
        } else {
            cp_wait<0>();
        }
        __syncthreads();

        const __half* Asm = As[kt & 1];
        const __half* Wsm = Ws[kt & 1];

#pragma unroll
        for (int ks = 0; ks < 2; ks++) {
            const int kb = ks * 16;
            uint32_t bfr[4][2];
#pragma unroll
            for (int nt = 0; nt < 4; nt++) {
                const __half* p = &Asm[(warpA * 32 + nt * 8 + g) * KPAD + kb + 2 * t4];
                bfr[nt][0] = *(const uint32_t*)p;
                bfr[nt][1] = *(const uint32_t*)(p + 8);
            }
            uint32_t afr[4][4];
#pragma unroll
            for (int mt = 0; mt < 4; mt++) {
                const __half* p = &Wsm[(warpW * 64 + mt * 16 + g) * KPAD + kb + 2 * t4];
                afr[mt][0] = *(const uint32_t*)p;
                afr[mt][1] = *(const uint32_t*)(p + 8 * KPAD);
                afr[mt][2] = *(const uint32_t*)(p + 8);
                afr[mt][3] = *(const uint32_t*)(p + 8 * KPAD + 8);
            }
#pragma unroll
            for (int mt = 0; mt < 4; mt++)
#pragma unroll
                for (int nt = 0; nt < 4; nt++) {
                    asm volatile(
                        "mma.sync.aligned.m16n8k16.row.col.f32.f16.f16.f32 "
                        "{%0,%1,%2,%3}, {%4,%5,%6,%7}, {%8,%9}, {%0,%1,%2,%3};\n"
                        : "+f"(acc[mt][nt][0]), "+f"(acc[mt][nt][1]),
                          "+f"(acc[mt][nt][2]), "+f"(acc[mt][nt][3])
                        : "r"(afr[mt][0]), "r"(afr[mt][1]), "r"(afr[mt][2]), "r"(afr[mt][3]),
                          "r"(bfr[nt][0]), "r"(bfr[nt][1]));
                }
        }
        __syncthreads();
    }

#pragma unroll
    for (int mt = 0; mt < 4; mt++) {
        const int wc = bn + warpW * 64 + mt * 16 + g;
        const bool c0ok = wc < N;
        const bool c8ok = (wc + 8) < N;
        const float b0 = c0ok ? bias[wc] : 0.f;
        const float b8 = c8ok ? bias[wc + 8] : 0.f;
#pragma unroll
        for (int nt = 0; nt < 4; nt++) {
            const int ar = bm + warpA * 32 + nt * 8 + 2 * t4;
#pragma unroll
            for (int half_i = 0; half_i < 2; half_i++) {
                const int r = ar + half_i;
                if (r >= Mdim) continue;
                float v0 = acc[mt][nt][0 + half_i] + b0;
                float v8 = acc[mt][nt][2 + half_i] + b8;
                if (RELU) { v0 = fmaxf(v0, 0.f); v8 = fmaxf(v8, 0.f); }
                if (HALF_OUT) {
                    if (c0ok) Ch[(size_t)r * N + wc] = __float2half(v0);
                    if (c8ok) Ch[(size_t)r * N + wc + 8] = __float2half(v8);
                } else {
                    if (c0ok) C[(size_t)r * N + wc] = v0;
                    if (c8ok) C[(size_t)r * N + wc + 8] = v8;
                }
            }
        }
    }
}

// ---------------- deformable attention core (fp16 value, half4 loads) ----------------
// One block per row; 8 warps = 8 heads; pt = lane>>3 (0..3), cg = lane&7.
// Each lane gathers 4 fp16 channels (8 bytes) per corner.
__global__ void __launch_bounds__(256)
deform_kernel(const __half* __restrict__ value,  // [B,L,NH,HD] fp16
              const float* __restrict__ refp,    // [B,L,NL,2]
              const float* __restrict__ offattn, // [M,288]
              __half* __restrict__ outh) {       // [M,256] fp16
    const int row = blockIdx.x;
    const int h = threadIdx.y;
    const int lane = threadIdx.x;
    const int b = row / LL;

    const float* oa = offattn + (size_t)row * 288;
    const float* lg = oa + 192 + h * 12;
    float lv = (lane < 12) ? lg[lane] : -INFINITY;
    float m = lv;
#pragma unroll
    for (int s = 16; s > 0; s >>= 1) m = fmaxf(m, __shfl_xor_sync(0xffffffffu, m, s));
    float e = (lane < 12) ? __expf(lv - m) : 0.f;
    float ssum = e;
#pragma unroll
    for (int s = 16; s > 0; s >>= 1) ssum += __shfl_xor_sync(0xffffffffu, ssum, s);
    float w12 = e / ssum;

    const float* offrow = oa + h * 24;
    const float* refrow = refp + (size_t)row * NLV * 2;
    const uint2* val4 = (const uint2*)value;   // 4 halves per entry

    const int pt = lane >> 3;   // 0..3
    const int cg = lane & 7;    // 0..7

    float4 acc = make_float4(0.f, 0.f, 0.f, 0.f);

#pragma unroll
    for (int l = 0; l < NLV; l++) {
        const int Hh = c_H[l], Ww = c_W[l], st = c_start[l];
        const int p = l * NPT + pt;
        const float rx = refrow[l * 2 + 0];
        const float ry = refrow[l * 2 + 1];
        const float ox = offrow[p * 2 + 0];
        const float oy = offrow[p * 2 + 1];
        const float aw = __shfl_sync(0xffffffffu, w12, p);

        float x = (rx + ox / (float)Ww) * (float)Ww - 0.5f;
        float y = (ry + oy / (float)Hh) * (float)Hh - 0.5f;
        float x0f = floorf(x), y0f = floorf(y);
        int x0 = (int)x0f, y0 = (int)y0f;
        int x1 = x0 + 1, y1 = y0 + 1;
        float wx1 = x - x0f, wy1 = y - y0f;
        float wx0 = 1.f - wx1, wy0 = 1.f - wy1;

        bool vx0 = (x0 >= 0) & (x0 < Ww);
        bool vx1 = (x1 >= 0) & (x1 < Ww);
        bool vy0 = (y0 >= 0) & (y0 < Hh);
        bool vy1 = (y1 >= 0) & (y1 < Hh);

        // half4 index: row_index*64 + h*8 + cg
        const size_t base = ((size_t)(b * LL + st)) * 64 + h * 8 + cg;
        uint2 u00 = make_uint2(0, 0), u10 = u00, u01 = u00, u11 = u00;
        if (vx0 & vy0) u00 = val4[base + (size_t)(y0 * Ww + x0) * 64];
        if (vx1 & vy0) u10 = val4[base + (size_t)(y0 * Ww + x1) * 64];
        if (vx0 & vy1) u01 = val4[base + (size_t)(y1 * Ww + x0) * 64];
        if (vx1 & vy1) u11 = val4[base + (size_t)(y1 * Ww + x1) * 64];

        const float w00 = wx0 * wy0 * aw, w10 = wx1 * wy0 * aw;
        const float w01 = wx0 * wy1 * aw, w11 = wx1 * wy1 * aw;

        float2 a0, a1;
        a0 = __half22float2(*(const __half2*)&u00.x);
        a1 = __half22float2(*(const __half2*)&u00.y);
        acc.x += a0.x * w00; acc.y += a0.y * w00; acc.z += a1.x * w00; acc.w += a1.y * w00;
        a0 = __half22float2(*(const __half2*)&u10.x);
        a1 = __half22float2(*(const __half2*)&u10.y);
        acc.x += a0.x * w10; acc.y += a0.y * w10; acc.z += a1.x * w10; acc.w += a1.y * w10;
        a0 = __half22float2(*(const __half2*)&u01.x);
        a1 = __half22float2(*(const __half2*)&u01.y);
        acc.x += a0.x * w01; acc.y += a0.y * w01; acc.z += a1.x * w01; acc.w += a1.y * w01;
        a0 = __half22float2(*(const __half2*)&u11.x);
        a1 = __half22float2(*(const __half2*)&u11.y);
        acc.x += a0.x * w11; acc.y += a0.y * w11; acc.z += a1.x * w11; acc.w += a1.y * w11;
    }

#pragma unroll
    for (int s = 8; s <= 16; s <<= 1) {
        acc.x += __shfl_xor_sync(0xffffffffu, acc.x, s);
        acc.y += __shfl_xor_sync(0xffffffffu, acc.y, s);
        acc.z += __shfl_xor_sync(0xffffffffu, acc.z, s);
        acc.w += __shfl_xor_sync(0xffffffffu, acc.w, s);
    }
    if (pt == 0) {
        __half2 h01 = __floats2half2_rn(acc.x, acc.y);
        __half2 h23 = __floats2half2_rn(acc.z, acc.w);
        __half2* dst = (__half2*)(outh + (size_t)row * DD + h * 32 + cg * 4);
        dst[0] = h01;
        dst[1] = h23;
    }
}

// ---------------- fused add + LayerNorm ----------------
__global__ void __launch_bounds__(256)
add_ln_kernel(const float* __restrict__ a, const float* __restrict__ b,
              const float* __restrict__ gamma, const float* __restrict__ beta,
              float* __restrict__ out, __half* __restrict__ outh) {
    const int row = blockIdx.x;
    const int t = threadIdx.x;
    float v = a[(size_t)row * DD + t] + b[(size_t)row * DD + t];

    float s = v, sq = v * v;
#pragma unroll
    for (int d = 16; d > 0; d >>= 1) {
        s += __shfl_xor_sync(0xffffffffu, s, d);
        sq += __shfl_xor_sync(0xffffffffu, sq, d);
    }
    __shared__ float ws[8], wsq[8];
    int wid = t >> 5, lane = t & 31;
    if (lane == 0) { ws[wid] = s; wsq[wid] = sq; }
    __syncthreads();
    if (t < 32) {
        float s2 = (t < 8) ? ws[t] : 0.f;
        float sq2 = (t < 8) ? wsq[t] : 0.f;
#pragma unroll
        for (int d = 4; d > 0; d >>= 1) {
            s2 += __shfl_xor_sync(0xffffffffu, s2, d);
            sq2 += __shfl_xor_sync(0xffffffffu, sq2, d);
        }
        if (t == 0) { ws[0] = s2; wsq[0] = sq2; }
    }
    __syncthreads();
    float mean = ws[0] * (1.f / DD);
    float var = wsq[0] * (1.f / DD) - mean * mean;
    float inv = rsqrtf(var + EPS);
    float r = (v - mean) * inv * gamma[t] + beta[t];
    out[(size_t)row * DD + t] = r;
    if (outh) outh[(size_t)row * DD + t] = __float2half(r);
}

// ---------------- launch ----------------
extern "C" void kernel_launch(void* const* d_in, const int* in_sizes, int n_in,
                              void* d_out, int out_size) {
    const float* src  = (const float*)d_in[0];
    const float* pos  = (const float*)d_in[1];
    const float* refp = (const float*)d_in[2];
    const float* Wv   = (const float*)d_in[3];
    const float* bv   = (const float*)d_in[4];
    const float* Woff = (const float*)d_in[5];
    const float* boff = (const float*)d_in[6];
    const float* Wattn= (const float*)d_in[7];
    const float* battn= (const float*)d_in[8];
    const float* Wout = (const float*)d_in[9];
    const float* bout = (const float*)d_in[10];
    const float* g1   = (const float*)d_in[11];
    const float* b1   = (const float*)d_in[12];
    const float* Wff1 = (const float*)d_in[13];
    const float* bff1 = (const float*)d_in[14];
    const float* Wff2 = (const float*)d_in[15];
    const float* bff2 = (const float*)d_in[16];
    const float* g2   = (const float*)d_in[17];
    const float* b2   = (const float*)d_in[18];
    float* out = (float*)d_out;

    __half *qh, *srch, *valh, *samph, *xh, *hh;
    __half *wvT, *woaT, *woutT, *wff1T, *wff2T;
    float *offattn, *x, *tmp, *boa;
    cudaGetSymbolAddress((void**)&qh, g_qh);
    cudaGetSymbolAddress((void**)&srch, g_srch);
    cudaGetSymbolAddress((void**)&valh, g_valh);
    cudaGetSymbolAddress((void**)&offattn, g_offattn);
    cudaGetSymbolAddress((void**)&samph, g_samph);
    cudaGetSymbolAddress((void**)&x, g_x);
    cudaGetSymbolAddress((void**)&xh, g_xh);
    cudaGetSymbolAddress((void**)&hh, g_hh);
    cudaGetSymbolAddress((void**)&tmp, g_tmp);
    cudaGetSymbolAddress((void**)&wvT, g_wvT);
    cudaGetSymbolAddress((void**)&woaT, g_woaT);
    cudaGetSymbolAddress((void**)&woutT, g_woutT);
    cudaGetSymbolAddress((void**)&wff1T, g_wff1T);
    cudaGetSymbolAddress((void**)&wff2T, g_wff2T);
    cudaGetSymbolAddress((void**)&boa, g_boa);

    // 1. all weight conversions in one launch
    cvt_all<<<(CVT_TOTAL + 255) / 256, 256>>>(Wv, Woff, Wattn, Wout, Wff1, Wff2, boff, battn);

    const int n = MM * DD;
    // 2. q/src fp16
    add_cvt_kernel<<<(n + 255) / 256, 256>>>(src, pos, qh, srch, n);

    dim3 blk(256);
    auto grid_for = [](int Mdim, int N) {
        return dim3((N + 127) / 128, (Mdim + 127) / 128);
    };

    // 3. value = src @ Wv + bv (fp16 out)
    gemm_f16<false, true><<<grid_for(MM, DD), blk>>>(srch, wvT, bv, nullptr, valh, MM, DD, DD);
    // 4. off|attn = q @ [Woff|Wattn] + [boff|battn]
    gemm_f16<false, false><<<grid_for(MM, 288), blk>>>(qh, woaT, boa, offattn, nullptr, MM, 288, DD);

    // 5. deformable sampling -> samp (fp16)
    deform_kernel<<<MM, dim3(32, 8)>>>(valh, refp, offattn, samph);

    // 6. attn_out = samp @ Wout + bout (fp32 tmp)
    gemm_f16<false, false><<<grid_for(MM, DD), blk>>>(samph, woutT, bout, tmp, nullptr, MM, DD, DD);

    // 7. x = LN(src + attn_out) -> fp32 + fp16
    add_ln_kernel<<<MM, 256>>>(src, tmp, g1, b1, x, xh);

    // 8. h = relu(x @ Wff1 + bff1) (fp16 out)
    gemm_f16<true, true><<<grid_for(MM, DFF), blk>>>(xh, wff1T, bff1, nullptr, hh, MM, DFF, DD);

    // 9. ff = h @ Wff2 + bff2 (fp32 tmp)
    gemm_f16<false, false><<<grid_for(MM, DD), blk>>>(hh, wff2T, bff2, tmp, nullptr, MM, DD, DFF);

    // 10. out = LN(x + ff)
    add_ln_kernel<<<MM, 256>>>(x, tmp, g2, b2, out, nullptr);
}

// round 7
// speedup vs baseline: 3.5361x; 1.0083x over previous
#include <cuda_runtime.h>
#include <cuda_fp16.h>
#include <cstdint>
#include <math.h>

// Problem constants
#define BB 4
#define LL 13125
#define MM (BB * LL)      // 52500 rows
#define DD 256
#define NH 8
#define HD 32
#define NLV 3
#define NPT 4
#define DFF 1024
#define EPS 1e-5f

__device__ __constant__ int c_H[NLV] = {100, 50, 25};
__device__ __constant__ int c_W[NLV] = {100, 50, 25};
__device__ __constant__ int c_start[NLV] = {0, 10000, 12500};

// ---------------- scratch ----------------
__device__ __half g_qh[MM * DD];
__device__ __half g_srch[MM * DD];
__device__ __half g_valh[MM * DD];
__device__ float  g_offattn[MM * 288];
__device__ __half g_samph[MM * DD];
__device__ float  g_x[MM * DD];
__device__ __half g_xh[MM * DD];
__device__ __half g_hh[MM * DFF];
__device__ float  g_tmp[MM * DD];
__device__ __half g_wvT[DD * DD];
__device__ __half g_woaT[288 * DD];
__device__ __half g_woutT[DD * DD];
__device__ __half g_wff1T[DFF * DD];
__device__ __half g_wff2T[DD * DFF];
__device__ float  g_boa[288];

// ---------------- fused weight convert/transpose + bias concat ----------------
#define CV0 (DD*DD)
#define CV1 (CV0 + DD*192)
#define CV2 (CV1 + DD*96)
#define CV3 (CV2 + DD*DD)
#define CV4 (CV3 + DD*DFF)
#define CV5 (CV4 + DFF*DD)
#define CVT_TOTAL (CV5 + 288)

__global__ void cvt_all(const float* __restrict__ Wv, const float* __restrict__ Woff,
                        const float* __restrict__ Wattn, const float* __restrict__ Wout,
                        const float* __restrict__ Wff1, const float* __restrict__ Wff2,
                        const float* __restrict__ boff, const float* __restrict__ battn) {
    int idx = blockIdx.x * blockDim.x + threadIdx.x;
    if (idx >= CVT_TOTAL) return;
    if (idx < CV0) {
        int k = idx / DD, n = idx % DD;
        g_wvT[(size_t)n * DD + k] = __float2half(Wv[idx]);
    } else if (idx < CV1) {
        int i = idx - CV0;
        int k = i / 192, n = i % 192;
        g_woaT[(size_t)n * DD + k] = __float2half(Woff[i]);
    } else if (idx < CV2) {
        int i = idx - CV1;
        int k = i / 96, n = i % 96;
        g_woaT[(size_t)(192 + n) * DD + k] = __float2half(Wattn[i]);
    } else if (idx < CV3) {
        int i = idx - CV2;
        int k = i / DD, n = i % DD;
        g_woutT[(size_t)n * DD + k] = __float2half(Wout[i]);
    } else if (idx < CV4) {
        int i = idx - CV3;
        int k = i / DFF, n = i % DFF;
        g_wff1T[(size_t)n * DD + k] = __float2half(Wff1[i]);
    } else if (idx < CV5) {
        int i = idx - CV4;
        int k = i / DD, n = i % DD;
        g_wff2T[(size_t)n * DFF + k] = __float2half(Wff2[i]);
    } else {
        int i = idx - CV5;
        g_boa[i] = (i < 192) ? boff[i] : battn[i - 192];
    }
}

// ---------------- fused q = src+pos (fp16) and src->fp16 ----------------
__global__ void add_cvt_kernel(const float* __restrict__ src, const float* __restrict__ pos,
                               __half* __restrict__ qh, __half* __restrict__ srch, int n) {
    int i = blockIdx.x * blockDim.x + threadIdx.x;
    if (i < n) {
        float s = src[i];
        qh[i] = __float2half(s + pos[i]);
        srch[i] = __float2half(s);
    }
}

// ================= FP16 tensor-core GEMM (ldmatrix) =================
#define BK 32
#define KPAD 40   // 80-byte row stride; ldmatrix conflict-free (offsets {0,5,2,7,4,1,6,3}*16 mod 128)

__device__ __forceinline__ void cp_async16(void* smem_ptr, const void* gmem_ptr, bool valid) {
    uint32_t saddr = (uint32_t)__cvta_generic_to_shared(smem_ptr);
    int sz = valid ? 16 : 0;
    asm volatile("cp.async.cg.shared.global [%0], [%1], 16, %2;\n"
                 :: "r"(saddr), "l"(gmem_ptr), "r"(sz));
}
__device__ __forceinline__ void cp_commit() {
    asm volatile("cp.async.commit_group;\n");
}
template <int N>
__device__ __forceinline__ void cp_wait() {
    asm volatile("cp.async.wait_group %0;\n" :: "n"(N));
}
__device__ __forceinline__ void ldsm_x4(uint32_t& r0, uint32_t& r1, uint32_t& r2, uint32_t& r3,
                                        uint32_t addr) {
    asm volatile("ldmatrix.sync.aligned.m8n8.x4.shared.b16 {%0,%1,%2,%3}, [%4];"
                 : "=r"(r0), "=r"(r1), "=r"(r2), "=r"(r3) : "r"(addr));
}
__device__ __forceinline__ void ldsm_x2(uint32_t& r0, uint32_t& r1, uint32_t addr) {
    asm volatile("ldmatrix.sync.aligned.m8n8.x2.shared.b16 {%0,%1}, [%2];"
                 : "=r"(r0), "=r"(r1) : "r"(addr));
}

template <bool RELU, bool HALF_OUT>
__global__ void __launch_bounds__(256, 2)
gemm_f16(const __half* __restrict__ Aact,  // [Mdim][K]
         const __half* __restrict__ Wt,    // [N][K]
         const float* __restrict__ bias,
         float* __restrict__ C,
         __half* __restrict__ Ch,
         int Mdim, int N, int K) {
    __shared__ __half As[2][128 * KPAD];   // act tile  [actrow][k]
    __shared__ __half Ws[2][128 * KPAD];   // weight tile [wcol][k]

    const int tid = threadIdx.x;
    const int lane = tid & 31;
    const int wid = tid >> 5;
    const int warpW = wid & 1;
    const int warpA = wid >> 1;
    const int g = lane >> 2;
    const int t4 = lane & 3;

    const int bm = blockIdx.y * 128;
    const int bn = blockIdx.x * 128;

    const int l_row = tid >> 1;
    const int l_kc0 = (tid & 1) * 2;

    const bool a_ok = (bm + l_row) < Mdim;
    const bool w_ok = (bn + l_row) < N;

    // ldmatrix per-lane offsets (in halves)
    // A (weights) x4: q = lane>>3; row = (q&1)*8 + (lane&7); col = (q>>1)*8
    const int a_ld_off = (((lane >> 3) & 1) * 8 + (lane & 7)) * KPAD + ((lane >> 4) * 8);
    // B (acts) x2: lb = lane&15; row = lb&7; col = (lb>>3)*8
    const int b_ld_off = ((lane & 7) * KPAD) + (((lane >> 3) & 1) * 8);

    float acc[4][4][4];
#pragma unroll
    for (int i = 0; i < 4; i++)
#pragma unroll
        for (int j = 0; j < 4; j++)
#pragma unroll
            for (int r = 0; r < 4; r++) acc[i][j][r] = 0.f;

    const int KT = K / BK;

    {
        const __half* ag = Aact + (size_t)(bm + l_row) * K + l_kc0 * 8;
        const __half* wg = Wt + (size_t)(bn + l_row) * K + l_kc0 * 8;
#pragma unroll
        for (int i = 0; i < 2; i++) {
            cp_async16(&As[0][l_row * KPAD + (l_kc0 + i) * 8], ag + i * 8, a_ok);
            cp_async16(&Ws[0][l_row * KPAD + (l_kc0 + i) * 8], wg + i * 8, w_ok);
        }
        cp_commit();
    }

    for (int kt = 0; kt < KT; kt++) {
        if (kt + 1 < KT) {
            const int k0 = (kt + 1) * BK;
            const int s = (kt + 1) & 1;
            const __half* ag = Aact + (size_t)(bm + l_row) * K + k0 + l_kc0 * 8;
            const __half* wg = Wt + (size_t)(bn + l_row) * K + k0 + l_kc0 * 8;
#pragma unroll
            for (int i = 0; i < 2; i++) {
                cp_async16(&As[s][l_row * KPAD + (l_kc0 + i) * 8], ag + i * 8, a_ok);
                cp_async16(&Ws[s][l_row * KPAD + (l_kc0 + i) * 8], wg + i * 8, w_ok);
            }
            cp_commit();
            cp_wait<1>();
        } else {
            cp_wait<0>();
        }
        __syncthreads();

        const uint32_t asBase = (uint32_t)__cvta_generic_to_shared(&As[kt & 1][0]);
        const uint32_t wsBase = (uint32_t)__cvta_generic_to_shared(&Ws[kt & 1][0]);

#pragma unroll
        for (int ks = 0; ks < 2; ks++) {
            const int kb = ks * 16;
            uint32_t bfr[4][2];
#pragma unroll
            for (int nt = 0; nt < 4; nt++) {
                const uint32_t addr = asBase +
                    2 * ((warpA * 32 + nt * 8) * KPAD + kb + b_ld_off);
                ldsm_x2(bfr[nt][0], bfr[nt][1], addr);
            }
            uint32_t afr[4][4];
#pragma unroll
            for (int mt = 0; mt < 4; mt++) {
                const uint32_t addr = wsBase +
                    2 * ((warpW * 64 + mt * 16) * KPAD + kb + a_ld_off);
                ldsm_x4(afr[mt][0], afr[mt][1], afr[mt][2], afr[mt][3], addr);
            }
#pragma unroll
            for (int mt = 0; mt < 4; mt++)
#pragma unroll
                for (int nt = 0; nt < 4; nt++) {
                    asm volatile(
                        "mma.sync.aligned.m16n8k16.row.col.f32.f16.f16.f32 "
                        "{%0,%1,%2,%3}, {%4,%5,%6,%7}, {%8,%9}, {%0,%1,%2,%3};\n"
                        : "+f"(acc[mt][nt][0]), "+f"(acc[mt][nt][1]),
                          "+f"(acc[mt][nt][2]), "+f"(acc[mt][nt][3])
                        : "r"(afr[mt][0]), "r"(afr[mt][1]), "r"(afr[mt][2]), "r"(afr[mt][3]),
                          "r"(bfr[nt][0]), "r"(bfr[nt][1]));
                }
        }
        __syncthreads();
    }

#pragma unroll
    for (int mt = 0; mt < 4; mt++) {
        const int wc = bn + warpW * 64 + mt * 16 + g;
        const bool c0ok = wc < N;
        const bool c8ok = (wc + 8) < N;
        const float b0 = c0ok ? bias[wc] : 0.f;
        const float b8 = c8ok ? bias[wc + 8] : 0.f;
#pragma unroll
        for (int nt = 0; nt < 4; nt++) {
            const int ar = bm + warpA * 32 + nt * 8 + 2 * t4;
#pragma unroll
            for (int half_i = 0; half_i < 2; half_i++) {
                const int r = ar + half_i;
                if (r >= Mdim) continue;
                float v0 = acc[mt][nt][0 + half_i] + b0;
                float v8 = acc[mt][nt][2 + half_i] + b8;
                if (RELU) { v0 = fmaxf(v0, 0.f); v8 = fmaxf(v8, 0.f); }
                if (HALF_OUT) {
                    if (c0ok) Ch[(size_t)r * N + wc] = __float2half(v0);
                    if (c8ok) Ch[(size_t)r * N + wc + 8] = __float2half(v8);
                } else {
                    if (c0ok) C[(size_t)r * N + wc] = v0;
                    if (c8ok) C[(size_t)r * N + wc + 8] = v8;
                }
            }
        }
    }
}

// ---------------- deformable attention core (fp16 value, half4 loads) ----------------
__global__ void __launch_bounds__(256)
deform_kernel(const __half* __restrict__ value,  // [B,L,NH,HD] fp16
              const float* __restrict__ refp,
              const float* __restrict__ offattn, // [M,288]
              __half* __restrict__ outh) {
    const int row = blockIdx.x;
    const int h = threadIdx.y;
    const int lane = threadIdx.x;
    const int b = row / LL;

    const float* oa = offattn + (size_t)row * 288;
    const float* lg = oa + 192 + h * 12;
    float lv = (lane < 12) ? lg[lane] : -INFINITY;
    float m = lv;
#pragma unroll
    for (int s = 16; s > 0; s >>= 1) m = fmaxf(m, __shfl_xor_sync(0xffffffffu, m, s));
    float e = (lane < 12) ? __expf(lv - m) : 0.f;
    float ssum = e;
#pragma unroll
    for (int s = 16; s > 0; s >>= 1) ssum += __shfl_xor_sync(0xffffffffu, ssum, s);
    float w12 = e / ssum;

    const float* offrow = oa + h * 24;
    const float* refrow = refp + (size_t)row * NLV * 2;
    const uint2* val4 = (const uint2*)value;

    const int pt = lane >> 3;
    const int cg = lane & 7;

    float4 acc = make_float4(0.f, 0.f, 0.f, 0.f);

#pragma unroll
    for (int l = 0; l < NLV; l++) {
        const int Hh = c_H[l], Ww = c_W[l], st = c_start[l];
        const int p = l * NPT + pt;
        const float rx = refrow[l * 2 + 0];
        const float ry = refrow[l * 2 + 1];
        const float ox = offrow[p * 2 + 0];
        const float oy = offrow[p * 2 + 1];
        const float aw = __shfl_sync(0xffffffffu, w12, p);

        float x = (rx + ox / (float)Ww) * (float)Ww - 0.5f;
        float y = (ry + oy / (float)Hh) * (float)Hh - 0.5f;
        float x0f = floorf(x), y0f = floorf(y);
        int x0 = (int)x0f, y0 = (int)y0f;
        int x1 = x0 + 1, y1 = y0 + 1;
        float wx1 = x - x0f, wy1 = y - y0f;
        float wx0 = 1.f - wx1, wy0 = 1.f - wy1;

        bool vx0 = (x0 >= 0) & (x0 < Ww);
        bool vx1 = (x1 >= 0) & (x1 < Ww);
        bool vy0 = (y0 >= 0) & (y0 < Hh);
        bool vy1 = (y1 >= 0) & (y1 < Hh);

        const size_t base = ((size_t)(b * LL + st)) * 64 + h * 8 + cg;
        uint2 u00 = make_uint2(0, 0), u10 = u00, u01 = u00, u11 = u00;
        if (vx0 & vy0) u00 = val4[base + (size_t)(y0 * Ww + x0) * 64];
        if (vx1 & vy0) u10 = val4[base + (size_t)(y0 * Ww + x1) * 64];
        if (vx0 & vy1) u01 = val4[base + (size_t)(y1 * Ww + x0) * 64];
        if (vx1 & vy1) u11 = val4[base + (size_t)(y1 * Ww + x1) * 64];

        const float w00 = wx0 * wy0 * aw, w10 = wx1 * wy0 * aw;
        const float w01 = wx0 * wy1 * aw, w11 = wx1 * wy1 * aw;

        float2 a0, a1;
        a0 = __half22float2(*(const __half2*)&u00.x);
        a1 = __half22float2(*(const __half2*)&u00.y);
        acc.x += a0.x * w00; acc.y += a0.y * w00; acc.z += a1.x * w00; acc.w += a1.y * w00;
        a0 = __half22float2(*(const __half2*)&u10.x);
        a1 = __half22float2(*(const __half2*)&u10.y);
        acc.x += a0.x * w10; acc.y += a0.y * w10; acc.z += a1.x * w10; acc.w += a1.y * w10;
        a0 = __half22float2(*(const __half2*)&u01.x);
        a1 = __half22float2(*(const __half2*)&u01.y);
        acc.x += a0.x * w01; acc.y += a0.y * w01; acc.z += a1.x * w01; acc.w += a1.y * w01;
        a0 = __half22float2(*(const __half2*)&u11.x);
        a1 = __half22float2(*(const __half2*)&u11.y);
        acc.x += a0.x * w11; acc.y += a0.y * w11; acc.z += a1.x * w11; acc.w += a1.y * w11;
    }

#pragma unroll
    for (int s = 8; s <= 16; s <<= 1) {
        acc.x += __shfl_xor_sync(0xffffffffu, acc.x, s);
        acc.y += __shfl_xor_sync(0xffffffffu, acc.y, s);
        acc.z += __shfl_xor_sync(0xffffffffu, acc.z, s);
        acc.w += __shfl_xor_sync(0xffffffffu, acc.w, s);
    }
    if (pt == 0) {
        __half2 h01 = __floats2half2_rn(acc.x, acc.y);
        __half2 h23 = __floats2half2_rn(acc.z, acc.w);
        __half2* dst = (__half2*)(outh + (size_t)row * DD + h * 32 + cg * 4);
        dst[0] = h01;
        dst[1] = h23;
    }
}

// ---------------- fused add + LayerNorm ----------------
__global__ void __launch_bounds__(256)
add_ln_kernel(const float* __restrict__ a, const float* __restrict__ b,
              const float* __restrict__ gamma, const float* __restrict__ beta,
              float* __restrict__ out, __half* __restrict__ outh) {
    const int row = blockIdx.x;
    const int t = threadIdx.x;
    float v = a[(size_t)row * DD + t] + b[(size_t)row * DD + t];

    float s = v, sq = v * v;
#pragma unroll
    for (int d = 16; d > 0; d >>= 1) {
        s += __shfl_xor_sync(0xffffffffu, s, d);
        sq += __shfl_xor_sync(0xffffffffu, sq, d);
    }
    __shared__ float ws[8], wsq[8];
    int wid = t >> 5, lane = t & 31;
    if (lane == 0) { ws[wid] = s; wsq[wid] = sq; }
    __syncthreads();
    if (t < 32) {
        float s2 = (t < 8) ? ws[t] : 0.f;
        float sq2 = (t < 8) ? wsq[t] : 0.f;
#pragma unroll
        for (int d = 4; d > 0; d >>= 1) {
            s2 += __shfl_xor_sync(0xffffffffu, s2, d);
            sq2 += __shfl_xor_sync(0xffffffffu, sq2, d);
        }
        if (t == 0) { ws[0] = s2; wsq[0] = sq2; }
    }
    __syncthreads();
    float mean = ws[0] * (1.f / DD);
    float var = wsq[0] * (1.f / DD) - mean * mean;
    float inv = rsqrtf(var + EPS);
    float r = (v - mean) * inv * gamma[t] + beta[t];
    out[(size_t)row * DD + t] = r;
    if (outh) outh[(size_t)row * DD + t] = __float2half(r);
}

// ---------------- launch ----------------
extern "C" void kernel_launch(void* const* d_in, const int* in_sizes, int n_in,
                              void* d_out, int out_size) {
    const float* src  = (const float*)d_in[0];
    const float* pos  = (const float*)d_in[1];
    const float* refp = (const float*)d_in[2];
    const float* Wv   = (const float*)d_in[3];
    const float* bv   = (const float*)d_in[4];
    const float* Woff = (const float*)d_in[5];
    const float* boff = (const float*)d_in[6];
    const float* Wattn= (const float*)d_in[7];
    const float* battn= (const float*)d_in[8];
    const float* Wout = (const float*)d_in[9];
    const float* bout = (const float*)d_in[10];
    const float* g1   = (const float*)d_in[11];
    const float* b1   = (const float*)d_in[12];
    const float* Wff1 = (const float*)d_in[13];
    const float* bff1 = (const float*)d_in[14];
    const float* Wff2 = (const float*)d_in[15];
    const float* bff2 = (const float*)d_in[16];
    const float* g2   = (const float*)d_in[17];
    const float* b2   = (const float*)d_in[18];
    float* out = (float*)d_out;

    __half *qh, *srch, *valh, *samph, *xh, *hh;
    __half *wvT, *woaT, *woutT, *wff1T, *wff2T;
    float *offattn, *x, *tmp, *boa;
    cudaGetSymbolAddress((void**)&qh, g_qh);
    cudaGetSymbolAddress((void**)&srch, g_srch);
    cudaGetSymbolAddress((void**)&valh, g_valh);
    cudaGetSymbolAddress((void**)&offattn, g_offattn);
    cudaGetSymbolAddress((void**)&samph, g_samph);
    cudaGetSymbolAddress((void**)&x, g_x);
    cudaGetSymbolAddress((void**)&xh, g_xh);
    cudaGetSymbolAddress((void**)&hh, g_hh);
    cudaGetSymbolAddress((void**)&tmp, g_tmp);
    cudaGetSymbolAddress((void**)&wvT, g_wvT);
    cudaGetSymbolAddress((void**)&woaT, g_woaT);
    cudaGetSymbolAddress((void**)&woutT, g_woutT);
    cudaGetSymbolAddress((void**)&wff1T, g_wff1T);
    cudaGetSymbolAddress((void**)&wff2T, g_wff2T);
    cudaGetSymbolAddress((void**)&boa, g_boa);

    cvt_all<<<(CVT_TOTAL + 255) / 256, 256>>>(Wv, Woff, Wattn, Wout, Wff1, Wff2, boff, battn);

    const int n = MM * DD;
    add_cvt_kernel<<<(n + 255) / 256, 256>>>(src, pos, qh, srch, n);

    dim3 blk(256);
    auto grid_for = [](int Mdim, int N) {
        return dim3((N + 127) / 128, (Mdim + 127) / 128);
    };

    gemm_f16<false, true><<<grid_for(MM, DD), blk>>>(srch, wvT, bv, nullptr, valh, MM, DD, DD);
    gemm_f16<false, false><<<grid_for(MM, 288), blk>>>(qh, woaT, boa, offattn, nullptr, MM, 288, DD);

    deform_kernel<<<MM, dim3(32, 8)>>>(valh, refp, offattn, samph);

    gemm_f16<false, false><<<grid_for(MM, DD), blk>>>(samph, woutT, bout, tmp, nullptr, MM, DD, DD);

    add_ln_kernel<<<MM, 256>>>(src, tmp, g1, b1, x, xh);

    gemm_f16<true, true><<<grid_for(MM, DFF), blk>>>(xh, wff1T, bff1, nullptr, hh, MM, DFF, DD);

    gemm_f16<false, false><<<grid_for(MM, DD), blk>>>(hh, wff2T, bff2, tmp, nullptr, MM, DD, DFF);

    add_ln_kernel<<<MM, 256>>>(x, tmp, g2, b2, out, nullptr);
}

// round 8
// speedup vs baseline: 3.6461x; 1.0311x over previous
#include <cuda_runtime.h>
#include <cuda_fp16.h>
#include <cstdint>
#include <math.h>

// Problem constants
#define BB 4
#define LL 13125
#define MM (BB * LL)      // 52500 rows
#define DD 256
#define NH 8
#define HD 32
#define NLV 3
#define NPT 4
#define DFF 1024
#define EPS 1e-5f

__device__ __constant__ int c_H[NLV] = {100, 50, 25};
__device__ __constant__ int c_W[NLV] = {100, 50, 25};
__device__ __constant__ int c_start[NLV] = {0, 10000, 12500};

// ---------------- scratch ----------------
__device__ __half g_qh[MM * DD];
__device__ __half g_srch[MM * DD];
__device__ __half g_valh[MM * DD];
__device__ float  g_offattn[MM * 288];
__device__ __half g_samph[MM * DD];
__device__ float  g_x[MM * DD];
__device__ __half g_xh[MM * DD];
__device__ __half g_hh[MM * DFF];
__device__ float  g_tmp[MM * DD];
__device__ __half g_wvT[DD * DD];
__device__ __half g_woaT[288 * DD];
__device__ __half g_woutT[DD * DD];
__device__ __half g_wff1T[DFF * DD];
__device__ __half g_wff2T[DD * DFF];
__device__ float  g_boa[288];

// ---------------- fused weight convert/transpose + bias concat ----------------
#define CV0 (DD*DD)
#define CV1 (CV0 + DD*192)
#define CV2 (CV1 + DD*96)
#define CV3 (CV2 + DD*DD)
#define CV4 (CV3 + DD*DFF)
#define CV5 (CV4 + DFF*DD)
#define CVT_TOTAL (CV5 + 288)

__global__ void cvt_all(const float* __restrict__ Wv, const float* __restrict__ Woff,
                        const float* __restrict__ Wattn, const float* __restrict__ Wout,
                        const float* __restrict__ Wff1, const float* __restrict__ Wff2,
                        const float* __restrict__ boff, const float* __restrict__ battn) {
    int idx = blockIdx.x * blockDim.x + threadIdx.x;
    if (idx >= CVT_TOTAL) return;
    if (idx < CV0) {
        int k = idx / DD, n = idx % DD;
        g_wvT[(size_t)n * DD + k] = __float2half(Wv[idx]);
    } else if (idx < CV1) {
        int i = idx - CV0;
        int k = i / 192, n = i % 192;
        g_woaT[(size_t)n * DD + k] = __float2half(Woff[i]);
    } else if (idx < CV2) {
        int i = idx - CV1;
        int k = i / 96, n = i % 96;
        g_woaT[(size_t)(192 + n) * DD + k] = __float2half(Wattn[i]);
    } else if (idx < CV3) {
        int i = idx - CV2;
        int k = i / DD, n = i % DD;
        g_woutT[(size_t)n * DD + k] = __float2half(Wout[i]);
    } else if (idx < CV4) {
        int i = idx - CV3;
        int k = i / DFF, n = i % DFF;
        g_wff1T[(size_t)n * DD + k] = __float2half(Wff1[i]);
    } else if (idx < CV5) {
        int i = idx - CV4;
        int k = i / DD, n = i % DD;
        g_wff2T[(size_t)n * DFF + k] = __float2half(Wff2[i]);
    } else {
        int i = idx - CV5;
        g_boa[i] = (i < 192) ? boff[i] : battn[i - 192];
    }
}

// ---------------- fused q = src+pos (fp16) and src->fp16 ----------------
__global__ void add_cvt_kernel(const float* __restrict__ src, const float* __restrict__ pos,
                               __half* __restrict__ qh, __half* __restrict__ srch, int n) {
    int i = blockIdx.x * blockDim.x + threadIdx.x;
    if (i < n) {
        float s = src[i];
        qh[i] = __float2half(s + pos[i]);
        srch[i] = __float2half(s);
    }
}

// ================= FP16 tensor-core GEMM (ldmatrix, 3-stage pipeline) =================
#define BK 32
#define KPAD 40        // 80-byte row stride; ldmatrix conflict-free
#define STAGES 3
#define TILE_HALVES (128 * KPAD)                 // per matrix per stage
#define GEMM_SMEM_BYTES (STAGES * 2 * TILE_HALVES * 2)

__device__ __forceinline__ void cp_async16(void* smem_ptr, const void* gmem_ptr, bool valid) {
    uint32_t saddr = (uint32_t)__cvta_generic_to_shared(smem_ptr);
    int sz = valid ? 16 : 0;
    asm volatile("cp.async.cg.shared.global [%0], [%1], 16, %2;\n"
                 :: "r"(saddr), "l"(gmem_ptr), "r"(sz));
}
__device__ __forceinline__ void cp_commit() {
    asm volatile("cp.async.commit_group;\n");
}
template <int N>
__device__ __forceinline__ void cp_wait() {
    asm volatile("cp.async.wait_group %0;\n" :: "n"(N));
}
__device__ __forceinline__ void ldsm_x4(uint32_t& r0, uint32_t& r1, uint32_t& r2, uint32_t& r3,
                                        uint32_t addr) {
    asm volatile("ldmatrix.sync.aligned.m8n8.x4.shared.b16 {%0,%1,%2,%3}, [%4];"
                 : "=r"(r0), "=r"(r1), "=r"(r2), "=r"(r3) : "r"(addr));
}
__device__ __forceinline__ void ldsm_x2(uint32_t& r0, uint32_t& r1, uint32_t addr) {
    asm volatile("ldmatrix.sync.aligned.m8n8.x2.shared.b16 {%0,%1}, [%2];"
                 : "=r"(r0), "=r"(r1) : "r"(addr));
}

template <bool RELU, bool HALF_OUT>
__global__ void __launch_bounds__(256, 2)
gemm_f16(const __half* __restrict__ Aact,  // [Mdim][K]
         const __half* __restrict__ Wt,    // [N][K]
         const float* __restrict__ bias,
         float* __restrict__ C,
         __half* __restrict__ Ch,
         int Mdim, int N, int K) {
    extern __shared__ __half sm[];
    __half* As = sm;                          // [STAGES][TILE_HALVES]
    __half* Ws = sm + STAGES * TILE_HALVES;   // [STAGES][TILE_HALVES]

    const int tid = threadIdx.x;
    const int lane = tid & 31;
    const int wid = tid >> 5;
    const int warpW = wid & 1;
    const int warpA = wid >> 1;
    const int g = lane >> 2;
    const int t4 = lane & 3;

    const int bm = blockIdx.y * 128;
    const int bn = blockIdx.x * 128;

    const int l_row = tid >> 1;
    const int l_kc0 = (tid & 1) * 2;

    const bool a_ok = (bm + l_row) < Mdim;
    const bool w_ok = (bn + l_row) < N;

    // ldmatrix per-lane offsets (in halves)
    const int a_ld_off = (((lane >> 3) & 1) * 8 + (lane & 7)) * KPAD + ((lane >> 4) * 8);
    const int b_ld_off = ((lane & 7) * KPAD) + (((lane >> 3) & 1) * 8);

    float acc[4][4][4];
#pragma unroll
    for (int i = 0; i < 4; i++)
#pragma unroll
        for (int j = 0; j < 4; j++)
#pragma unroll
            for (int r = 0; r < 4; r++) acc[i][j][r] = 0.f;

    const int KT = K / BK;

    // helper to issue a tile load into stage s
    auto load_tile = [&](int kt, int s) {
        const int k0 = kt * BK;
        const __half* ag = Aact + (size_t)(bm + l_row) * K + k0 + l_kc0 * 8;
        const __half* wg = Wt + (size_t)(bn + l_row) * K + k0 + l_kc0 * 8;
        __half* as = As + s * TILE_HALVES + l_row * KPAD + l_kc0 * 8;
        __half* ws = Ws + s * TILE_HALVES + l_row * KPAD + l_kc0 * 8;
#pragma unroll
        for (int i = 0; i < 2; i++) {
            cp_async16(as + i * 8, ag + i * 8, a_ok);
            cp_async16(ws + i * 8, wg + i * 8, w_ok);
        }
        cp_commit();
    };

    // prologue: tiles 0,1 -> stages 0,1
    load_tile(0, 0);
    if (KT > 1) load_tile(1, 1);

    for (int kt = 0; kt < KT; kt++) {
        // wait until tile kt complete
        if (kt + 1 < KT) cp_wait<1>();
        else cp_wait<0>();
        __syncthreads();   // tile kt visible to all; previous iter's compute done -> stage (kt+2)%3 free

        if (kt + 2 < KT) load_tile(kt + 2, (kt + 2) % STAGES);

        const int s = kt % STAGES;
        const uint32_t asBase = (uint32_t)__cvta_generic_to_shared(As + s * TILE_HALVES);
        const uint32_t wsBase = (uint32_t)__cvta_generic_to_shared(Ws + s * TILE_HALVES);

#pragma unroll
        for (int ks = 0; ks < 2; ks++) {
            const int kb = ks * 16;
            uint32_t bfr[4][2];
#pragma unroll
            for (int nt = 0; nt < 4; nt++) {
                const uint32_t addr = asBase +
                    2 * ((warpA * 32 + nt * 8) * KPAD + kb + b_ld_off);
                ldsm_x2(bfr[nt][0], bfr[nt][1], addr);
            }
            uint32_t afr[4][4];
#pragma unroll
            for (int mt = 0; mt < 4; mt++) {
                const uint32_t addr = wsBase +
                    2 * ((warpW * 64 + mt * 16) * KPAD + kb + a_ld_off);
                ldsm_x4(afr[mt][0], afr[mt][1], afr[mt][2], afr[mt][3], addr);
            }
#pragma unroll
            for (int mt = 0; mt < 4; mt++)
#pragma unroll
                for (int nt = 0; nt < 4; nt++) {
                    asm volatile(
                        "mma.sync.aligned.m16n8k16.row.col.f32.f16.f16.f32 "
                        "{%0,%1,%2,%3}, {%4,%5,%6,%7}, {%8,%9}, {%0,%1,%2,%3};\n"
                        : "+f"(acc[mt][nt][0]), "+f"(acc[mt][nt][1]),
                          "+f"(acc[mt][nt][2]), "+f"(acc[mt][nt][3])
                        : "r"(afr[mt][0]), "r"(afr[mt][1]), "r"(afr[mt][2]), "r"(afr[mt][3]),
                          "r"(bfr[nt][0]), "r"(bfr[nt][1]));
                }
        }
    }

#pragma unroll
    for (int mt = 0; mt < 4; mt++) {
        const int wc = bn + warpW * 64 + mt * 16 + g;
        const bool c0ok = wc < N;
        const bool c8ok = (wc + 8) < N;
        const float b0 = c0ok ? bias[wc] : 0.f;
        const float b8 = c8ok ? bias[wc + 8] : 0.f;
#pragma unroll
        for (int nt = 0; nt < 4; nt++) {
            const int ar = bm + warpA * 32 + nt * 8 + 2 * t4;
#pragma unroll
            for (int half_i = 0; half_i < 2; half_i++) {
                const int r = ar + half_i;
                if (r >= Mdim) continue;
                float v0 = acc[mt][nt][0 + half_i] + b0;
                float v8 = acc[mt][nt][2 + half_i] + b8;
                if (RELU) { v0 = fmaxf(v0, 0.f); v8 = fmaxf(v8, 0.f); }
                if (HALF_OUT) {
                    if (c0ok) Ch[(size_t)r * N + wc] = __float2half(v0);
                    if (c8ok) Ch[(size_t)r * N + wc + 8] = __float2half(v8);
                } else {
                    if (c0ok) C[(size_t)r * N + wc] = v0;
                    if (c8ok) C[(size_t)r * N + wc + 8] = v8;
                }
            }
        }
    }
}

// ---------------- deformable attention core (fp16 value, half4 loads) ----------------
__global__ void __launch_bounds__(256)
deform_kernel(const __half* __restrict__ value,  // [B,L,NH,HD] fp16
              const float* __restrict__ refp,
              const float* __restrict__ offattn, // [M,288]
              __half* __restrict__ outh) {
    const int row = blockIdx.x;
    const int h = threadIdx.y;
    const int lane = threadIdx.x;
    const int b = row / LL;

    const float* oa = offattn + (size_t)row * 288;
    const float* lg = oa + 192 + h * 12;
    float lv = (lane < 12) ? lg[lane] : -INFINITY;
    float m = lv;
#pragma unroll
    for (int s = 16; s > 0; s >>= 1) m = fmaxf(m, __shfl_xor_sync(0xffffffffu, m, s));
    float e = (lane < 12) ? __expf(lv - m) : 0.f;
    float ssum = e;
#pragma unroll
    for (int s = 16; s > 0; s >>= 1) ssum += __shfl_xor_sync(0xffffffffu, ssum, s);
    float w12 = e / ssum;

    const float* offrow = oa + h * 24;
    const float* refrow = refp + (size_t)row * NLV * 2;
    const uint2* val4 = (const uint2*)value;

    const int pt = lane >> 3;
    const int cg = lane & 7;

    float4 acc = make_float4(0.f, 0.f, 0.f, 0.f);

#pragma unroll
    for (int l = 0; l < NLV; l++) {
        const int Hh = c_H[l], Ww = c_W[l], st = c_start[l];
        const int p = l * NPT + pt;
        const float rx = refrow[l * 2 + 0];
        const float ry = refrow[l * 2 + 1];
        const float ox = offrow[p * 2 + 0];
        const float oy = offrow[p * 2 + 1];
        const float aw = __shfl_sync(0xffffffffu, w12, p);

        float x = (rx + ox / (float)Ww) * (float)Ww - 0.5f;
        float y = (ry + oy / (float)Hh) * (float)Hh - 0.5f;
        float x0f = floorf(x), y0f = floorf(y);
        int x0 = (int)x0f, y0 = (int)y0f;
        int x1 = x0 + 1, y1 = y0 + 1;
        float wx1 = x - x0f, wy1 = y - y0f;
        float wx0 = 1.f - wx1, wy0 = 1.f - wy1;

        bool vx0 = (x0 >= 0) & (x0 < Ww);
        bool vx1 = (x1 >= 0) & (x1 < Ww);
        bool vy0 = (y0 >= 0) & (y0 < Hh);
        bool vy1 = (y1 >= 0) & (y1 < Hh);

        const size_t base = ((size_t)(b * LL + st)) * 64 + h * 8 + cg;
        uint2 u00 = make_uint2(0, 0), u10 = u00, u01 = u00, u11 = u00;
        if (vx0 & vy0) u00 = val4[base + (size_t)(y0 * Ww + x0) * 64];
        if (vx1 & vy0) u10 = val4[base + (size_t)(y0 * Ww + x1) * 64];
        if (vx0 & vy1) u01 = val4[base + (size_t)(y1 * Ww + x0) * 64];
        if (vx1 & vy1) u11 = val4[base + (size_t)(y1 * Ww + x1) * 64];

        const float w00 = wx0 * wy0 * aw, w10 = wx1 * wy0 * aw;
        const float w01 = wx0 * wy1 * aw, w11 = wx1 * wy1 * aw;

        float2 a0, a1;
        a0 = __half22float2(*(const __half2*)&u00.x);
        a1 = __half22float2(*(const __half2*)&u00.y);
        acc.x += a0.x * w00; acc.y += a0.y * w00; acc.z += a1.x * w00; acc.w += a1.y * w00;
        a0 = __half22float2(*(const __half2*)&u10.x);
        a1 = __half22float2(*(const __half2*)&u10.y);
        acc.x += a0.x * w10; acc.y += a0.y * w10; acc.z += a1.x * w10; acc.w += a1.y * w10;
        a0 = __half22float2(*(const __half2*)&u01.x);
        a1 = __half22float2(*(const __half2*)&u01.y);
        acc.x += a0.x * w01; acc.y += a0.y * w01; acc.z += a1.x * w01; acc.w += a1.y * w01;
        a0 = __half22float2(*(const __half2*)&u11.x);
        a1 = __half22float2(*(const __half2*)&u11.y);
        acc.x += a0.x * w11; acc.y += a0.y * w11; acc.z += a1.x * w11; acc.w += a1.y * w11;
    }

#pragma unroll
    for (int s = 8; s <= 16; s <<= 1) {
        acc.x += __shfl_xor_sync(0xffffffffu, acc.x, s);
        acc.y += __shfl_xor_sync(0xffffffffu, acc.y, s);
        acc.z += __shfl_xor_sync(0xffffffffu, acc.z, s);
        acc.w += __shfl_xor_sync(0xffffffffu, acc.w, s);
    }
    if (pt == 0) {
        __half2 h01 = __floats2half2_rn(acc.x, acc.y);
        __half2 h23 = __floats2half2_rn(acc.z, acc.w);
        __half2* dst = (__half2*)(outh + (size_t)row * DD + h * 32 + cg * 4);
        dst[0] = h01;
        dst[1] = h23;
    }
}

// ---------------- fused add + LayerNorm ----------------
__global__ void __launch_bounds__(256)
add_ln_kernel(const float* __restrict__ a, const float* __restrict__ b,
              const float* __restrict__ gamma, const float* __restrict__ beta,
              float* __restrict__ out, __half* __restrict__ outh) {
    const int row = blockIdx.x;
    const int t = threadIdx.x;
    float v = a[(size_t)row * DD + t] + b[(size_t)row * DD + t];

    float s = v, sq = v * v;
#pragma unroll
    for (int d = 16; d > 0; d >>= 1) {
        s += __shfl_xor_sync(0xffffffffu, s, d);
        sq += __shfl_xor_sync(0xffffffffu, sq, d);
    }
    __shared__ float ws[8], wsq[8];
    int wid = t >> 5, lane = t & 31;
    if (lane == 0) { ws[wid] = s; wsq[wid] = sq; }
    __syncthreads();
    if (t < 32) {
        float s2 = (t < 8) ? ws[t] : 0.f;
        float sq2 = (t < 8) ? wsq[t] : 0.f;
#pragma unroll
        for (int d = 4; d > 0; d >>= 1) {
            s2 += __shfl_xor_sync(0xffffffffu, s2, d);
            sq2 += __shfl_xor_sync(0xffffffffu, sq2, d);
        }
        if (t == 0) { ws[0] = s2; wsq[0] = sq2; }
    }
    __syncthreads();
    float mean = ws[0] * (1.f / DD);
    float var = wsq[0] * (1.f / DD) - mean * mean;
    float inv = rsqrtf(var + EPS);
    float r = (v - mean) * inv * gamma[t] + beta[t];
    out[(size_t)row * DD + t] = r;
    if (outh) outh[(size_t)row * DD + t] = __float2half(r);
}

// ---------------- launch ----------------
extern "C" void kernel_launch(void* const* d_in, const int* in_sizes, int n_in,
                              void* d_out, int out_size) {
    const float* src  = (const float*)d_in[0];
    const float* pos  = (const float*)d_in[1];
    const float* refp = (const float*)d_in[2];
    const float* Wv   = (const float*)d_in[3];
    const float* bv   = (const float*)d_in[4];
    const float* Woff = (const float*)d_in[5];
    const float* boff = (const float*)d_in[6];
    const float* Wattn= (const float*)d_in[7];
    const float* battn= (const float*)d_in[8];
    const float* Wout = (const float*)d_in[9];
    const float* bout = (const float*)d_in[10];
    const float* g1   = (const float*)d_in[11];
    const float* b1   = (const float*)d_in[12];
    const float* Wff1 = (const float*)d_in[13];
    const float* bff1 = (const float*)d_in[14];
    const float* Wff2 = (const float*)d_in[15];
    const float* bff2 = (const float*)d_in[16];
    const float* g2   = (const float*)d_in[17];
    const float* b2   = (const float*)d_in[18];
    float* out = (float*)d_out;

    __half *qh, *srch, *valh, *samph, *xh, *hh;
    __half *wvT, *woaT, *woutT, *wff1T, *wff2T;
    float *offattn, *x, *tmp, *boa;
    cudaGetSymbolAddress((void**)&qh, g_qh);
    cudaGetSymbolAddress((void**)&srch, g_srch);
    cudaGetSymbolAddress((void**)&valh, g_valh);
    cudaGetSymbolAddress((void**)&offattn, g_offattn);
    cudaGetSymbolAddress((void**)&samph, g_samph);
    cudaGetSymbolAddress((void**)&x, g_x);
    cudaGetSymbolAddress((void**)&xh, g_xh);
    cudaGetSymbolAddress((void**)&hh, g_hh);
    cudaGetSymbolAddress((void**)&tmp, g_tmp);
    cudaGetSymbolAddress((void**)&wvT, g_wvT);
    cudaGetSymbolAddress((void**)&woaT, g_woaT);
    cudaGetSymbolAddress((void**)&woutT, g_woutT);
    cudaGetSymbolAddress((void**)&wff1T, g_wff1T);
    cudaGetSymbolAddress((void**)&wff2T, g_wff2T);
    cudaGetSymbolAddress((void**)&boa, g_boa);

    cudaFuncSetAttribute(gemm_f16<false, false>,
                         cudaFuncAttributeMaxDynamicSharedMemorySize, GEMM_SMEM_BYTES);
    cudaFuncSetAttribute(gemm_f16<false, true>,
                         cudaFuncAttributeMaxDynamicSharedMemorySize, GEMM_SMEM_BYTES);
    cudaFuncSetAttribute(gemm_f16<true, true>,
                         cudaFuncAttributeMaxDynamicSharedMemorySize, GEMM_SMEM_BYTES);

    cvt_all<<<(CVT_TOTAL + 255) / 256, 256>>>(Wv, Woff, Wattn, Wout, Wff1, Wff2, boff, battn);

    const int n = MM * DD;
    add_cvt_kernel<<<(n + 255) / 256, 256>>>(src, pos, qh, srch, n);

    dim3 blk(256);
    auto grid_for = [](int Mdim, int N) {
        return dim3((N + 127) / 128, (Mdim + 127) / 128);
    };

    gemm_f16<false, true><<<grid_for(MM, DD), blk, GEMM_SMEM_BYTES>>>(srch, wvT, bv, nullptr, valh, MM, DD, DD);
    gemm_f16<false, false><<<grid_for(MM, 288), blk, GEMM_SMEM_BYTES>>>(qh, woaT, boa, offattn, nullptr, MM, 288, DD);

    deform_kernel<<<MM, dim3(32, 8)>>>(valh, refp, offattn, samph);

    gemm_f16<false, false><<<grid_for(MM, DD), blk, GEMM_SMEM_BYTES>>>(samph, woutT, bout, tmp, nullptr, MM, DD, DD);

    add_ln_kernel<<<MM, 256>>>(src, tmp, g1, b1, x, xh);

    gemm_f16<true, true><<<grid_for(MM, DFF), blk, GEMM_SMEM_BYTES>>>(xh, wff1T, bff1, nullptr, hh, MM, DFF, DD);

    gemm_f16<false, false><<<grid_for(MM, DD), blk, GEMM_SMEM_BYTES>>>(hh, wff2T, bff2, tmp, nullptr, MM, DD, DFF);

    add_ln_kernel<<<MM, 256>>>(x, tmp, g2, b2, out, nullptr);
}

// round 10
// speedup vs baseline: 4.1058x; 1.1261x over previous
#include <cuda_runtime.h>
#include <cuda_fp16.h>
#include <cstdint>
#include <math.h>

// Problem constants
#define BB 4
#define LL 13125
#define MM (BB * LL)      // 52500 rows
#define DD 256
#define NH 8
#define HD 32
#define NLV 3
#define NPT 4
#define DFF 1024
#define EPS 1e-5f

__device__ __constant__ int c_H[NLV] = {100, 50, 25};
__device__ __constant__ int c_W[NLV] = {100, 50, 25};
__device__ __constant__ int c_start[NLV] = {0, 10000, 12500};

// ---------------- scratch ----------------
__device__ __half g_qh[MM * DD];
__device__ __half g_srch[MM * DD];
__device__ __half g_valh[MM * DD];
__device__ float  g_offattn[MM * 288];
__device__ __half g_samph[MM * DD];
__device__ float  g_x[MM * DD];
__device__ __half g_xh[MM * DD];
__device__ __half g_hh[MM * DFF];
__device__ __half g_wvT[DD * DD];
__device__ __half g_woaT[288 * DD];
__device__ __half g_woutT[DD * DD];
__device__ __half g_wff1T[DFF * DD];
__device__ __half g_wff2T[DD * DFF];
__device__ float  g_boa[288];

// ---------------- fused weight convert/transpose + bias concat ----------------
#define CV0 (DD*DD)
#define CV1 (CV0 + DD*192)
#define CV2 (CV1 + DD*96)
#define CV3 (CV2 + DD*DD)
#define CV4 (CV3 + DD*DFF)
#define CV5 (CV4 + DFF*DD)
#define CVT_TOTAL (CV5 + 288)

__global__ void cvt_all(const float* __restrict__ Wv, const float* __restrict__ Woff,
                        const float* __restrict__ Wattn, const float* __restrict__ Wout,
                        const float* __restrict__ Wff1, const float* __restrict__ Wff2,
                        const float* __restrict__ boff, const float* __restrict__ battn) {
    int idx = blockIdx.x * blockDim.x + threadIdx.x;
    if (idx >= CVT_TOTAL) return;
    if (idx < CV0) {
        int k = idx / DD, n = idx % DD;
        g_wvT[(size_t)n * DD + k] = __float2half(Wv[idx]);
    } else if (idx < CV1) {
        int i = idx - CV0;
        int k = i / 192, n = i % 192;
        g_woaT[(size_t)n * DD + k] = __float2half(Woff[i]);
    } else if (idx < CV2) {
        int i = idx - CV1;
        int k = i / 96, n = i % 96;
        g_woaT[(size_t)(192 + n) * DD + k] = __float2half(Wattn[i]);
    } else if (idx < CV3) {
        int i = idx - CV2;
        int k = i / DD, n = i % DD;
        g_woutT[(size_t)n * DD + k] = __float2half(Wout[i]);
    } else if (idx < CV4) {
        int i = idx - CV3;
        int k = i / DFF, n = i % DFF;
        g_wff1T[(size_t)n * DD + k] = __float2half(Wff1[i]);
    } else if (idx < CV5) {
        int i = idx - CV4;
        int k = i / DD, n = i % DD;
        g_wff2T[(size_t)n * DFF + k] = __float2half(Wff2[i]);
    } else {
        int i = idx - CV5;
        g_boa[i] = (i < 192) ? boff[i] : battn[i - 192];
    }
}

// ---------------- fused q = src+pos (fp16) and src->fp16 ----------------
__global__ void add_cvt_kernel(const float* __restrict__ src, const float* __restrict__ pos,
                               __half* __restrict__ qh, __half* __restrict__ srch, int n) {
    int i = blockIdx.x * blockDim.x + threadIdx.x;
    if (i < n) {
        float s = src[i];
        qh[i] = __float2half(s + pos[i]);
        srch[i] = __float2half(s);
    }
}

// ================= common GEMM helpers =================
#define BK 32
#define KPAD 40   // 80-byte row stride; ldmatrix conflict-free

__device__ __forceinline__ void cp_async16(void* smem_ptr, const void* gmem_ptr, bool valid) {
    uint32_t saddr = (uint32_t)__cvta_generic_to_shared(smem_ptr);
    int sz = valid ? 16 : 0;
    asm volatile("cp.async.cg.shared.global [%0], [%1], 16, %2;\n"
                 :: "r"(saddr), "l"(gmem_ptr), "r"(sz));
}
__device__ __forceinline__ void cp_async16r(uint32_t saddr, const void* gmem_ptr, bool valid) {
    int sz = valid ? 16 : 0;
    asm volatile("cp.async.cg.shared.global [%0], [%1], 16, %2;\n"
                 :: "r"(saddr), "l"(gmem_ptr), "r"(sz));
}
__device__ __forceinline__ void cp_commit() {
    asm volatile("cp.async.commit_group;\n");
}
template <int N>
__device__ __forceinline__ void cp_wait() {
    asm volatile("cp.async.wait_group %0;\n" :: "n"(N));
}
__device__ __forceinline__ void ldsm_x4(uint32_t& r0, uint32_t& r1, uint32_t& r2, uint32_t& r3,
                                        uint32_t addr) {
    asm volatile("ldmatrix.sync.aligned.m8n8.x4.shared.b16 {%0,%1,%2,%3}, [%4];"
                 : "=r"(r0), "=r"(r1), "=r"(r2), "=r"(r3) : "r"(addr));
}
__device__ __forceinline__ void ldsm_x2(uint32_t& r0, uint32_t& r1, uint32_t addr) {
    asm volatile("ldmatrix.sync.aligned.m8n8.x2.shared.b16 {%0,%1}, [%2];"
                 : "=r"(r0), "=r"(r1) : "r"(addr));
}
#define MMA16816(acc, afr, bfr) \
    asm volatile( \
        "mma.sync.aligned.m16n8k16.row.col.f32.f16.f16.f32 " \
        "{%0,%1,%2,%3}, {%4,%5,%6,%7}, {%8,%9}, {%0,%1,%2,%3};\n" \
        : "+f"((acc)[0]), "+f"((acc)[1]), "+f"((acc)[2]), "+f"((acc)[3]) \
        : "r"((afr)[0]), "r"((afr)[1]), "r"((afr)[2]), "r"((afr)[3]), \
          "r"((bfr)[0]), "r"((bfr)[1]))

// ================= generic FP16 GEMM (R8-proven: 128x128, 3-stage) =================
#define STAGES 3
#define TILE_HALVES (128 * KPAD)
#define GEMM_SMEM_BYTES (STAGES * 2 * TILE_HALVES * 2)

template <bool RELU, bool HALF_OUT>
__global__ void __launch_bounds__(256, 2)
gemm_f16(const __half* __restrict__ Aact,  // [Mdim][K]
         const __half* __restrict__ Wt,    // [N][K]
         const float* __restrict__ bias,
         float* __restrict__ C,
         __half* __restrict__ Ch,
         int Mdim, int N, int K) {
    extern __shared__ __half sm[];
    __half* As = sm;
    __half* Ws = sm + STAGES * TILE_HALVES;

    const int tid = threadIdx.x;
    const int lane = tid & 31;
    const int wid = tid >> 5;
    const int warpW = wid & 1;
    const int warpA = wid >> 1;
    const int g = lane >> 2;
    const int t4 = lane & 3;

    const int bm = blockIdx.y * 128;
    const int bn = blockIdx.x * 128;

    const int l_row = tid >> 1;
    const int l_kc0 = (tid & 1) * 2;

    const bool a_ok = (bm + l_row) < Mdim;
    const bool w_ok = (bn + l_row) < N;

    const int a_ld_off = (((lane >> 3) & 1) * 8 + (lane & 7)) * KPAD + ((lane >> 4) * 8);
    const int b_ld_off = ((lane & 7) * KPAD) + (((lane >> 3) & 1) * 8);

    float acc[4][4][4];
#pragma unroll
    for (int i = 0; i < 4; i++)
#pragma unroll
        for (int j = 0; j < 4; j++)
#pragma unroll
            for (int r = 0; r < 4; r++) acc[i][j][r] = 0.f;

    const int KT = K / BK;

    auto load_tile = [&](int kt, int s) {
        const int k0 = kt * BK;
        const __half* ag = Aact + (size_t)(bm + l_row) * K + k0 + l_kc0 * 8;
        const __half* wg = Wt + (size_t)(bn + l_row) * K + k0 + l_kc0 * 8;
        __half* as = As + s * TILE_HALVES + l_row * KPAD + l_kc0 * 8;
        __half* ws = Ws + s * TILE_HALVES + l_row * KPAD + l_kc0 * 8;
#pragma unroll
        for (int i = 0; i < 2; i++) {
            cp_async16(as + i * 8, ag + i * 8, a_ok);
            cp_async16(ws + i * 8, wg + i * 8, w_ok);
        }
        cp_commit();
    };

    load_tile(0, 0);
    if (KT > 1) load_tile(1, 1);

    for (int kt = 0; kt < KT; kt++) {
        if (kt + 1 < KT) cp_wait<1>();
        else cp_wait<0>();
        __syncthreads();

        if (kt + 2 < KT) load_tile(kt + 2, (kt + 2) % STAGES);

        const int s = kt % STAGES;
        const uint32_t asBase = (uint32_t)__cvta_generic_to_shared(As + s * TILE_HALVES);
        const uint32_t wsBase = (uint32_t)__cvta_generic_to_shared(Ws + s * TILE_HALVES);

#pragma unroll
        for (int ks = 0; ks < 2; ks++) {
            const int kb = ks * 16;
            uint32_t bfr[4][2];
#pragma unroll
            for (int nt = 0; nt < 4; nt++) {
                const uint32_t addr = asBase +
                    2 * ((warpA * 32 + nt * 8) * KPAD + kb + b_ld_off);
                ldsm_x2(bfr[nt][0], bfr[nt][1], addr);
            }
            uint32_t afr[4][4];
#pragma unroll
            for (int mt = 0; mt < 4; mt++) {
                const uint32_t addr = wsBase +
                    2 * ((warpW * 64 + mt * 16) * KPAD + kb + a_ld_off);
                ldsm_x4(afr[mt][0], afr[mt][1], afr[mt][2], afr[mt][3], addr);
            }
#pragma unroll
            for (int mt = 0; mt < 4; mt++)
#pragma unroll
                for (int nt = 0; nt < 4; nt++)
                    MMA16816(acc[mt][nt], afr[mt], bfr[nt]);
        }
    }

#pragma unroll
    for (int mt = 0; mt < 4; mt++) {
        const int wc = bn + warpW * 64 + mt * 16 + g;
        const bool c0ok = wc < N;
        const bool c8ok = (wc + 8) < N;
        const float b0 = c0ok ? bias[wc] : 0.f;
        const float b8 = c8ok ? bias[wc + 8] : 0.f;
#pragma unroll
        for (int nt = 0; nt < 4; nt++) {
            const int ar = bm + warpA * 32 + nt * 8 + 2 * t4;
#pragma unroll
            for (int half_i = 0; half_i < 2; half_i++) {
                const int r = ar + half_i;
                if (r >= Mdim) continue;
                float v0 = acc[mt][nt][0 + half_i] + b0;
                float v8 = acc[mt][nt][2 + half_i] + b8;
                if (RELU) { v0 = fmaxf(v0, 0.f); v8 = fmaxf(v8, 0.f); }
                if (HALF_OUT) {
                    if (c0ok) Ch[(size_t)r * N + wc] = __float2half(v0);
                    if (c8ok) Ch[(size_t)r * N + wc + 8] = __float2half(v8);
                } else {
                    if (c0ok) C[(size_t)r * N + wc] = v0;
                    if (c8ok) C[(size_t)r * N + wc + 8] = v8;
                }
            }
        }
    }
}

// ================= fused GEMM + bias + residual + LayerNorm (N fixed = 256) =================
// Block tile 64 rows x 256 cols, 8 warps: warpW = wid&3 (64 cols each), warpA = wid>>2 (32 rows each).
// Epilogue: acc += bias + residual; row mean/var via shfl + smem; out = LN * gamma + beta.
#define GLN_A_HALVES (64 * KPAD)
#define GLN_W_HALVES (256 * KPAD)
#define GLN_STAGE_HALVES (GLN_A_HALVES + GLN_W_HALVES)
#define GLN_SMEM_BYTES (STAGES * GLN_STAGE_HALVES * 2)

template <bool HALF_OUT>
__global__ void __launch_bounds__(256, 2)
gemm_ln_f16(const __half* __restrict__ Aact,   // [Mdim][K]
            const __half* __restrict__ Wt,     // [256][K]
            const float* __restrict__ bias,    // [256]
            const float* __restrict__ Resid,   // [Mdim][256] fp32
            const float* __restrict__ gamma,
            const float* __restrict__ beta,
            float* __restrict__ OutF,          // [Mdim][256] fp32
            __half* __restrict__ OutH,         // optional fp16
            int Mdim, int K) {
    extern __shared__ __half sm[];
    __shared__ float2 lnb[64][4];

    const int tid = threadIdx.x;
    const int lane = tid & 31;
    const int wid = tid >> 5;
    const int warpW = wid & 3;     // 0..3 -> 64-col group
    const int warpA = wid >> 2;    // 0..1 -> 32-row group
    const int g = lane >> 2;
    const int t4 = lane & 3;

    const int bm = blockIdx.y * 64;

    const int a_ld_off = (((lane >> 3) & 1) * 8 + (lane & 7)) * KPAD + ((lane >> 4) * 8);
    const int b_ld_off = ((lane & 7) * KPAD) + (((lane >> 3) & 1) * 8);

    const uint32_t smBase = (uint32_t)__cvta_generic_to_shared(sm);

    float acc[4][4][4];
#pragma unroll
    for (int i = 0; i < 4; i++)
#pragma unroll
        for (int j = 0; j < 4; j++)
#pragma unroll
            for (int r = 0; r < 4; r++) acc[i][j][r] = 0.f;

    const int KT = K / BK;

    // loader: 64 A rows (256 chunks) + 256 W rows (1024 chunks) = 1280 16B-chunks / 256 thr = 5 each
    auto load_tile = [&](int kt, int s) {
        const int k0 = kt * BK;
        const uint32_t st = smBase + (uint32_t)(s * GLN_STAGE_HALVES * 2);
#pragma unroll
        for (int i = 0; i < 5; i++) {
            int c = tid + i * 256;
            if (c < 256) {
                int row = c >> 2, kc = c & 3;
                cp_async16r(st + (uint32_t)((row * KPAD + kc * 8) * 2),
                            Aact + (size_t)(bm + row) * K + k0 + kc * 8,
                            (bm + row) < Mdim);
            } else {
                int cc = c - 256;
                int row = cc >> 2, kc = cc & 3;
                cp_async16r(st + (uint32_t)((GLN_A_HALVES + row * KPAD + kc * 8) * 2),
                            Wt + (size_t)row * K + k0 + kc * 8, true);
            }
        }
        cp_commit();
    };

    load_tile(0, 0);
    if (KT > 1) load_tile(1, 1);

    for (int kt = 0; kt < KT; kt++) {
        if (kt + 1 < KT) cp_wait<1>();
        else cp_wait<0>();
        __syncthreads();

        if (kt + 2 < KT) load_tile(kt + 2, (kt + 2) % STAGES);

        const uint32_t asBase = smBase + (uint32_t)((kt % STAGES) * GLN_STAGE_HALVES * 2);
        const uint32_t wsBase = asBase + (uint32_t)(GLN_A_HALVES * 2);

#pragma unroll
        for (int ks = 0; ks < 2; ks++) {
            const int kb = ks * 16;
            uint32_t bfr[4][2];
#pragma unroll
            for (int nt = 0; nt < 4; nt++) {
                const uint32_t addr = asBase +
                    2 * ((warpA * 32 + nt * 8) * KPAD + kb + b_ld_off);
                ldsm_x2(bfr[nt][0], bfr[nt][1], addr);
            }
            uint32_t afr[4][4];
#pragma unroll
            for (int mt = 0; mt < 4; mt++) {
                const uint32_t addr = wsBase +
                    2 * ((warpW * 64 + mt * 16) * KPAD + kb + a_ld_off);
                ldsm_x4(afr[mt][0], afr[mt][1], afr[mt][2], afr[mt][3], addr);
            }
#pragma unroll
            for (int mt = 0; mt < 4; mt++)
#pragma unroll
                for (int nt = 0; nt < 4; nt++)
                    MMA16816(acc[mt][nt], afr[mt], bfr[nt]);
        }
    }

    // ---- fused epilogue ----
    // bias + residual into acc. element (mt, nt, idx=half+2*colhi):
    //   row = bm + warpA*32 + nt*8 + 2*t4 + half ; col = warpW*64 + mt*16 + g + 8*colhi
    float bcolv[4][2], gcol[4][2], betacol[4][2];
#pragma unroll
    for (int mt = 0; mt < 4; mt++)
#pragma unroll
        for (int ch = 0; ch < 2; ch++) {
            int col = warpW * 64 + mt * 16 + g + 8 * ch;
            bcolv[mt][ch] = bias[col];
            gcol[mt][ch] = gamma[col];
            betacol[mt][ch] = beta[col];
        }

    float s_arr[4][2], q_arr[4][2];
#pragma unroll
    for (int nt = 0; nt < 4; nt++)
#pragma unroll
        for (int hf = 0; hf < 2; hf++) {
            const int row = bm + warpA * 32 + nt * 8 + 2 * t4 + hf;
            const bool rok = row < Mdim;
            float ls = 0.f, lq = 0.f;
#pragma unroll
            for (int mt = 0; mt < 4; mt++)
#pragma unroll
                for (int ch = 0; ch < 2; ch++) {
                    const int col = warpW * 64 + mt * 16 + g + 8 * ch;
                    float v = acc[mt][nt][hf + 2 * ch] + bcolv[mt][ch];
                    if (rok) v += Resid[(size_t)row * 256 + col];
                    acc[mt][nt][hf + 2 * ch] = v;
                    ls += v; lq += v * v;
                }
            // reduce over g (8 lanes sharing this row): xor 4, 8, 16
#pragma unroll
            for (int msk = 4; msk <= 16; msk <<= 1) {
                ls += __shfl_xor_sync(0xffffffffu, ls, msk);
                lq += __shfl_xor_sync(0xffffffffu, lq, msk);
            }
            s_arr[nt][hf] = ls;
            q_arr[nt][hf] = lq;
        }
    if (g == 0) {
#pragma unroll
        for (int nt = 0; nt < 4; nt++)
#pragma unroll
            for (int hf = 0; hf < 2; hf++) {
                int lrow = warpA * 32 + nt * 8 + 2 * t4 + hf;
                lnb[lrow][warpW] = make_float2(s_arr[nt][hf], q_arr[nt][hf]);
            }
    }
    __syncthreads();

#pragma unroll
    for (int nt = 0; nt < 4; nt++)
#pragma unroll
        for (int hf = 0; hf < 2; hf++) {
            const int lrow = warpA * 32 + nt * 8 + 2 * t4 + hf;
            const int row = bm + lrow;
            float ss = 0.f, qq = 0.f;
#pragma unroll
            for (int w = 0; w < 4; w++) {
                float2 p = lnb[lrow][w];
                ss += p.x; qq += p.y;
            }
            const float mean = ss * (1.f / 256.f);
            const float var = qq * (1.f / 256.f) - mean * mean;
            const float inv = rsqrtf(var + EPS);
            if (row < Mdim) {
#pragma unroll
                for (int mt = 0; mt < 4; mt++)
#pragma unroll
                    for (int ch = 0; ch < 2; ch++) {
                        const int col = warpW * 64 + mt * 16 + g + 8 * ch;
                        float r = (acc[mt][nt][hf + 2 * ch] - mean) * inv * gcol[mt][ch]
                                  + betacol[mt][ch];
                        OutF[(size_t)row * 256 + col] = r;
                        if (HALF_OUT) OutH[(size_t)row * 256 + col] = __float2half(r);
                    }
            }
        }
}

// ---------------- deformable attention core (fp16 value, half4 loads) ----------------
__global__ void __launch_bounds__(256)
deform_kernel(const __half* __restrict__ value,
              const float* __restrict__ refp,
              const float* __restrict__ offattn,
              __half* __restrict__ outh) {
    const int row = blockIdx.x;
    const int h = threadIdx.y;
    const int lane = threadIdx.x;
    const int b = row / LL;

    const float* oa = offattn + (size_t)row * 288;
    const float* lg = oa + 192 + h * 12;
    float lv = (lane < 12) ? lg[lane] : -INFINITY;
    float m = lv;
#pragma unroll
    for (int s = 16; s > 0; s >>= 1) m = fmaxf(m, __shfl_xor_sync(0xffffffffu, m, s));
    float e = (lane < 12) ? __expf(lv - m) : 0.f;
    float ssum = e;
#pragma unroll
    for (int s = 16; s > 0; s >>= 1) ssum += __shfl_xor_sync(0xffffffffu, ssum, s);
    float w12 = e / ssum;

    const float* offrow = oa + h * 24;
    const float* refrow = refp + (size_t)row * NLV * 2;
    const uint2* val4 = (const uint2*)value;

    const int pt = lane >> 3;
    const int cg = lane & 7;

    float4 acc = make_float4(0.f, 0.f, 0.f, 0.f);

#pragma unroll
    for (int l = 0; l < NLV; l++) {
        const int Hh = c_H[l], Ww = c_W[l], st = c_start[l];
        const int p = l * NPT + pt;
        const float rx = refrow[l * 2 + 0];
        const float ry = refrow[l * 2 + 1];
        const float ox = offrow[p * 2 + 0];
        const float oy = offrow[p * 2 + 1];
        const float aw = __shfl_sync(0xffffffffu, w12, p);

        float x = (rx + ox / (float)Ww) * (float)Ww - 0.5f;
        float y = (ry + oy / (float)Hh) * (float)Hh - 0.5f;
        float x0f = floorf(x), y0f = floorf(y);
        int x0 = (int)x0f, y0 = (int)y0f;
        int x1 = x0 + 1, y1 = y0 + 1;
        float wx1 = x - x0f, wy1 = y - y0f;
        float wx0 = 1.f - wx1, wy0 = 1.f - wy1;

        bool vx0 = (x0 >= 0) & (x0 < Ww);
        bool vx1 = (x1 >= 0) & (x1 < Ww);
        bool vy0 = (y0 >= 0) & (y0 < Hh);
        bool vy1 = (y1 >= 0) & (y1 < Hh);

        const size_t base = ((size_t)(b * LL + st)) * 64 + h * 8 + cg;
        uint2 u00 = make_uint2(0, 0), u10 = u00, u01 = u00, u11 = u00;
        if (vx0 & vy0) u00 = val4[base + (size_t)(y0 * Ww + x0) * 64];
        if (vx1 & vy0) u10 = val4[base + (size_t)(y0 * Ww + x1) * 64];
        if (vx0 & vy1) u01 = val4[base + (size_t)(y1 * Ww + x0) * 64];
        if (vx1 & vy1) u11 = val4[base + (size_t)(y1 * Ww + x1) * 64];

        const float w00 = wx0 * wy0 * aw, w10 = wx1 * wy0 * aw;
        const float w01 = wx0 * wy1 * aw, w11 = wx1 * wy1 * aw;

        float2 a0, a1;
        a0 = __half22float2(*(const __half2*)&u00.x);
        a1 = __half22float2(*(const __half2*)&u00.y);
        acc.x += a0.x * w00; acc.y += a0.y * w00; acc.z += a1.x * w00; acc.w += a1.y * w00;
        a0 = __half22float2(*(const __half2*)&u10.x);
        a1 = __half22float2(*(const __half2*)&u10.y);
        acc.x += a0.x * w10; acc.y += a0.y * w10; acc.z += a1.x * w10; acc.w += a1.y * w10;
        a0 = __half22float2(*(const __half2*)&u01.x);
        a1 = __half22float2(*(const __half2*)&u01.y);
        acc.x += a0.x * w01; acc.y += a0.y * w01; acc.z += a1.x * w01; acc.w += a1.y * w01;
        a0 = __half22float2(*(const __half2*)&u11.x);
        a1 = __half22float2(*(const __half2*)&u11.y);
        acc.x += a0.x * w11; acc.y += a0.y * w11; acc.z += a1.x * w11; acc.w += a1.y * w11;
    }

#pragma unroll
    for (int s = 8; s <= 16; s <<= 1) {
        acc.x += __shfl_xor_sync(0xffffffffu, acc.x, s);
        acc.y += __shfl_xor_sync(0xffffffffu, acc.y, s);
        acc.z += __shfl_xor_sync(0xffffffffu, acc.z, s);
        acc.w += __shfl_xor_sync(0xffffffffu, acc.w, s);
    }
    if (pt == 0) {
        __half2 h01 = __floats2half2_rn(acc.x, acc.y);
        __half2 h23 = __floats2half2_rn(acc.z, acc.w);
        __half2* dst = (__half2*)(outh + (size_t)row * DD + h * 32 + cg * 4);
        dst[0] = h01;
        dst[1] = h23;
    }
}

// ---------------- launch ----------------
extern "C" void kernel_launch(void* const* d_in, const int* in_sizes, int n_in,
                              void* d_out, int out_size) {
    const float* src  = (const float*)d_in[0];
    const float* pos  = (const float*)d_in[1];
    const float* refp = (const float*)d_in[2];
    const float* Wv   = (const float*)d_in[3];
    const float* bv   = (const float*)d_in[4];
    const float* Woff = (const float*)d_in[5];
    const float* boff = (const float*)d_in[6];
    const float* Wattn= (const float*)d_in[7];
    const float* battn= (const float*)d_in[8];
    const float* Wout = (const float*)d_in[9];
    const float* bout = (const float*)d_in[10];
    const float* g1   = (const float*)d_in[11];
    const float* b1   = (const float*)d_in[12];
    const float* Wff1 = (const float*)d_in[13];
    const float* bff1 = (const float*)d_in[14];
    const float* Wff2 = (const float*)d_in[15];
    const float* bff2 = (const float*)d_in[16];
    const float* g2   = (const float*)d_in[17];
    const float* b2   = (const float*)d_in[18];
    float* out = (float*)d_out;

    __half *qh, *srch, *valh, *samph, *xh, *hh;
    __half *wvT, *woaT, *woutT, *wff1T, *wff2T;
    float *offattn, *x, *boa;
    cudaGetSymbolAddress((void**)&qh, g_qh);
    cudaGetSymbolAddress((void**)&srch, g_srch);
    cudaGetSymbolAddress((void**)&valh, g_valh);
    cudaGetSymbolAddress((void**)&offattn, g_offattn);
    cudaGetSymbolAddress((void**)&samph, g_samph);
    cudaGetSymbolAddress((void**)&x, g_x);
    cudaGetSymbolAddress((void**)&xh, g_xh);
    cudaGetSymbolAddress((void**)&hh, g_hh);
    cudaGetSymbolAddress((void**)&wvT, g_wvT);
    cudaGetSymbolAddress((void**)&woaT, g_woaT);
    cudaGetSymbolAddress((void**)&woutT, g_woutT);
    cudaGetSymbolAddress((void**)&wff1T, g_wff1T);
    cudaGetSymbolAddress((void**)&wff2T, g_wff2T);
    cudaGetSymbolAddress((void**)&boa, g_boa);

    cudaFuncSetAttribute(gemm_f16<false, false>,
                         cudaFuncAttributeMaxDynamicSharedMemorySize, GEMM_SMEM_BYTES);
    cudaFuncSetAttribute(gemm_f16<false, true>,
                         cudaFuncAttributeMaxDynamicSharedMemorySize, GEMM_SMEM_BYTES);
    cudaFuncSetAttribute(gemm_f16<true, true>,
                         cudaFuncAttributeMaxDynamicSharedMemorySize, GEMM_SMEM_BYTES);
    cudaFuncSetAttribute(gemm_ln_f16<true>,
                         cudaFuncAttributeMaxDynamicSharedMemorySize, GLN_SMEM_BYTES);
    cudaFuncSetAttribute(gemm_ln_f16<false>,
                         cudaFuncAttributeMaxDynamicSharedMemorySize, GLN_SMEM_BYTES);

    cvt_all<<<(CVT_TOTAL + 255) / 256, 256>>>(Wv, Woff, Wattn, Wout, Wff1, Wff2, boff, battn);

    const int n = MM * DD;
    add_cvt_kernel<<<(n + 255) / 256, 256>>>(src, pos, qh, srch, n);

    dim3 blk(256);
    auto grid_for = [](int Mdim, int N) {
        return dim3((N + 127) / 128, (Mdim + 127) / 128);
    };

    // value = src @ Wv + bv (fp16 out)
    gemm_f16<false, true><<<grid_for(MM, DD), blk, GEMM_SMEM_BYTES>>>(srch, wvT, bv, nullptr, valh, MM, DD, DD);
    // off|attn = q @ [Woff|Wattn] + boa
    gemm_f16<false, false><<<grid_for(MM, 288), blk, GEMM_SMEM_BYTES>>>(qh, woaT, boa, offattn, nullptr, MM, 288, DD);

    deform_kernel<<<MM, dim3(32, 8)>>>(valh, refp, offattn, samph);

    // x = LN(src + samp @ Wout + bout)  -> fp32 x + fp16 xh (fused)
    gemm_ln_f16<true><<<dim3(1, (MM + 63) / 64), blk, GLN_SMEM_BYTES>>>(
        samph, woutT, bout, src, g1, b1, x, xh, MM, DD);

    // h = relu(x @ Wff1 + bff1) (fp16 out)
    gemm_f16<true, true><<<grid_for(MM, DFF), blk, GEMM_SMEM_BYTES>>>(xh, wff1T, bff1, nullptr, hh, MM, DFF, DD);

    // out = LN(x + h @ Wff2 + bff2)  (fused, fp32 only)
    gemm_ln_f16<false><<<dim3(1, (MM + 63) / 64), blk, GLN_SMEM_BYTES>>>(
        hh, wff2T, bff2, x, g2, b2, out, nullptr, MM, DFF);
}